// round 8
// baseline (speedup 1.0000x reference)
#include <cuda_runtime.h>
#include <cuda_fp16.h>
#include <math.h>
#include <stdint.h>

// Problem constants
#define NH   2
#define DKH  96
#define D    192
#define T    4096
#define B    16
#define BANK 1000

// Scratch (static device allocations)
__device__ __half    g_q16[B * T * D];        // scaled Q, [b][t][d] fp16
__device__ __half    g_attn16[B * T * D];     // attention out pre-Wo, [b][t][d] fp16
__device__ __half    g_k16T[NH * BANK * DKH]; // K, [h][s][dk] fp16
__device__ __half    g_v16[NH * DKH * BANK];  // V, [h][dk][s] fp16
__device__ uint32_t  g_Wq16[D * (D / 2)];     // alpha_q * Wq, [o][k2] h2
__device__ uint32_t  g_Wo16[D * (D / 2)];     // Wo, [o][k2] h2
__device__ float     g_bq[D];                 // alpha_q * bq

__device__ __forceinline__ float ex2f(float x) {
    float r; asm("ex2.approx.ftz.f32 %0, %1;" : "=f"(r) : "f"(x)); return r;
}
__device__ __forceinline__ uint32_t h2bits(float a, float b) {
    __half2 h = __floats2half2_rn(a, b);
    return *(uint32_t*)&h;
}
// m16n8k16 fp16 MMA, f32 accumulate in place.
__device__ __forceinline__ void mma16(float d[4],
                                      uint32_t a0, uint32_t a1, uint32_t a2, uint32_t a3,
                                      uint32_t b0, uint32_t b1) {
    asm volatile("mma.sync.aligned.m16n8k16.row.col.f32.f16.f16.f32 "
                 "{%0,%1,%2,%3}, {%4,%5,%6,%7}, {%8,%9}, {%0,%1,%2,%3};"
                 : "+f"(d[0]), "+f"(d[1]), "+f"(d[2]), "+f"(d[3])
                 : "r"(a0), "r"(a1), "r"(a2), "r"(a3), "r"(b0), "r"(b1));
}

// ---------------------------------------------------------------------------
// Kernel 0: weight prep. Converts Wq (scaled by alpha_q) and Wo to fp16 h2.
// grid (2), block 256
// ---------------------------------------------------------------------------
__global__ void wprep_kernel(const float* __restrict__ Wq, const float* __restrict__ bq,
                             const float* __restrict__ Wo, float alpha_q) {
    int which = blockIdx.x;
    const float* W = which ? Wo : Wq;
    uint32_t*  W16 = which ? g_Wo16 : g_Wq16;
    float alpha = which ? 1.0f : alpha_q;
    for (int i = threadIdx.x; i < D * (D / 2); i += 256) {
        int o = i / (D / 2), k2 = i % (D / 2);
        W16[o * (D / 2) + k2] = h2bits(alpha * W[o * D + 2 * k2],
                                       alpha * W[o * D + 2 * k2 + 1]);
    }
    if (which == 0)
        for (int i = threadIdx.x; i < D; i += 256) g_bq[i] = alpha_q * bq[i];
}

// ---------------------------------------------------------------------------
// Kernel 1: K/V projection of memory bank (batch-independent) -> fp16.
// K written transposed [h][s][dk], V as [h][dk][s].
// grid (4, 24, 2), block 256
// ---------------------------------------------------------------------------
__global__ void __launch_bounds__(256) kv_proj_kernel(
        const float* __restrict__ mb,
        const float* __restrict__ Wk, const float* __restrict__ bk,
        const float* __restrict__ Wv, const float* __restrict__ bv) {
    __shared__ float wks[4][192];
    __shared__ float wvs[4][192];

    int s   = blockIdx.x * 256 + threadIdx.x;
    int dk0 = blockIdx.y * 4;
    int h   = blockIdx.z;
    int row0 = h * DKH + dk0;

    for (int i = threadIdx.x; i < 4 * 192; i += 256) {
        int j = i / 192, c = i % 192;
        wks[j][c] = Wk[(row0 + j) * D + c];
        wvs[j][c] = Wv[(row0 + j) * D + c];
    }
    __syncthreads();
    if (s >= BANK) return;

    float ak[4] = {0.f, 0.f, 0.f, 0.f};
    float av[4] = {0.f, 0.f, 0.f, 0.f};
    #pragma unroll 4
    for (int c = 0; c < D; c++) {
        float x = mb[c * BANK + s];
        #pragma unroll
        for (int j = 0; j < 4; j++) {
            ak[j] = fmaf(wks[j][c], x, ak[j]);
            av[j] = fmaf(wvs[j][c], x, av[j]);
        }
    }
    __half hk[4];
    #pragma unroll
    for (int j = 0; j < 4; j++) {
        hk[j] = __float2half_rn(ak[j] + bk[row0 + j]);
        g_v16[((size_t)h * DKH + dk0 + j) * BANK + s] = __float2half_rn(av[j] + bv[row0 + j]);
    }
    *(uint2*)&g_k16T[((size_t)h * BANK + s) * DKH + dk0] = *(uint2*)hk;
}

// ---------------------------------------------------------------------------
// Kernel 2/4: channel projection, single-stage full-K fp16 m16n8k16.
// D[t][o] = X[t][k] * W16[o][k]^T; Y = D + bias  (alpha pre-folded into W16).
// CTA: 256 thr; tile t=128 x o=192, full K=192 resident in SMEM.
// SMEM (h2 words, pitch 100): Ws2[192][100], Xs2[128][100] -> 128000 B dyn.
// Warps wm(2) x wn(4): 4 m16(t) x 6 n8(o) per warp; 12 k-steps, 288 HMMA.
// grid (32, 1, 16)
// ---------------------------------------------------------------------------
#define PJP2 100
#define SMEM_PROJ_BYTES ((192 * PJP2 + 128 * PJP2) * 4)

__global__ void __launch_bounds__(256) proj16_kernel(
        const uint32_t* __restrict__ W16, const float* __restrict__ bias,
        const float* __restrict__ Xf, int src_half,
        float* __restrict__ Yf, int dst_half) {
    extern __shared__ uint32_t ps[];
    uint32_t* Ws2 = ps;                 // 192*100
    uint32_t* Xs2 = ps + 192 * PJP2;    // 128*100

    int tid  = threadIdx.x;
    int lane = tid & 31;
    int warp = tid >> 5;
    int g    = lane >> 2;
    int tg   = lane & 3;
    int wm   = warp >> 2;   // t: 64 each
    int wn   = warp & 3;    // o: 48 each

    int b  = blockIdx.z;
    int t0 = blockIdx.x * 128;
    const float* Xb = Xf + (size_t)b * D * T;
    const __half* Ab = g_attn16 + (size_t)b * T * D;

    // ---- Stage W (uint4 copies from prepped fp16) ----
    for (int i = tid; i < 4608; i += 256) {
        int o = i / 24, c = i % 24;
        uint4 v = *(const uint4*)(W16 + o * 96 + c * 4);
        *(uint4*)&Ws2[o * PJP2 + c * 4] = v;
    }
    // ---- Stage X ----
    if (src_half == 0) {
        // fp32 z [d][t]: transpose-convert to [t][k2]
        for (int i = tid; i < 3072; i += 256) {
            int k2 = i >> 5, t4 = i & 31;
            float4 xa = *(const float4*)(Xb + (size_t)(2 * k2)     * T + t0 + t4 * 4);
            float4 xb = *(const float4*)(Xb + (size_t)(2 * k2 + 1) * T + t0 + t4 * 4);
            Xs2[(t4 * 4 + 0) * PJP2 + k2] = h2bits(xa.x, xb.x);
            Xs2[(t4 * 4 + 1) * PJP2 + k2] = h2bits(xa.y, xb.y);
            Xs2[(t4 * 4 + 2) * PJP2 + k2] = h2bits(xa.z, xb.z);
            Xs2[(t4 * 4 + 3) * PJP2 + k2] = h2bits(xa.w, xb.w);
        }
    } else {
        // fp16 attn [t][d]: straight uint4 row copies
        for (int i = tid; i < 3072; i += 256) {
            int t = i / 24, c = i % 24;
            uint4 v = *(const uint4*)(Ab + (size_t)(t0 + t) * D + c * 8);
            *(uint4*)&Xs2[t * PJP2 + c * 4] = v;
        }
    }
    __syncthreads();

    float acc[4][6][4];
    #pragma unroll
    for (int mt = 0; mt < 4; mt++)
        #pragma unroll
        for (int nt = 0; nt < 6; nt++)
            #pragma unroll
            for (int c = 0; c < 4; c++) acc[mt][nt][c] = 0.f;

    #pragma unroll
    for (int ks = 0; ks < 12; ks++) {
        int kk2 = ks * 8;
        uint32_t bw[6][2];
        #pragma unroll
        for (int nt = 0; nt < 6; nt++) {
            int on = wn * 48 + nt * 8;
            bw[nt][0] = Ws2[(on + g) * PJP2 + kk2 + tg];
            bw[nt][1] = Ws2[(on + g) * PJP2 + kk2 + tg + 4];
        }
        #pragma unroll
        for (int mt = 0; mt < 4; mt++) {
            int tm = wm * 64 + mt * 16;
            uint32_t a0 = Xs2[(tm + g)     * PJP2 + kk2 + tg];
            uint32_t a1 = Xs2[(tm + g + 8) * PJP2 + kk2 + tg];
            uint32_t a2 = Xs2[(tm + g)     * PJP2 + kk2 + tg + 4];
            uint32_t a3 = Xs2[(tm + g + 8) * PJP2 + kk2 + tg + 4];
            #pragma unroll
            for (int nt = 0; nt < 6; nt++)
                mma16(acc[mt][nt], a0, a1, a2, a3, bw[nt][0], bw[nt][1]);
        }
    }

    // Epilogue: y = acc + bias (alpha pre-folded)
    #pragma unroll
    for (int mt = 0; mt < 4; mt++) {
        int t_lo = wm * 64 + mt * 16 + g;
        int t_hi = t_lo + 8;
        #pragma unroll
        for (int nt = 0; nt < 6; nt++) {
            int o0 = wn * 48 + nt * 8 + 2 * tg;
            float b0v = bias[o0], b1v = bias[o0 + 1];
            float y0 = acc[mt][nt][0] + b0v;
            float y1 = acc[mt][nt][1] + b1v;
            float y2 = acc[mt][nt][2] + b0v;
            float y3 = acc[mt][nt][3] + b1v;
            if (dst_half) {
                *(uint32_t*)&g_q16[((size_t)b * T + t0 + t_lo) * D + o0] = h2bits(y0, y1);
                *(uint32_t*)&g_q16[((size_t)b * T + t0 + t_hi) * D + o0] = h2bits(y2, y3);
            } else {
                Yf[((size_t)b * D + o0)     * T + t0 + t_lo] = y0;
                Yf[((size_t)b * D + o0 + 1) * T + t0 + t_lo] = y1;
                Yf[((size_t)b * D + o0)     * T + t0 + t_hi] = y2;
                Yf[((size_t)b * D + o0 + 1) * T + t0 + t_hi] = y3;
            }
        }
    }
}

// ---------------------------------------------------------------------------
// Kernel 3: fp16 mma.sync attention, no-max softmax. s-chunks of 128.
// CTA: 256 thr / 8 warps, 256 queries of one (b,h); warp owns 32 q rows.
// SMEM (h2 words): Qs[256][52], Ks[128][52], Vs[96][68], Ps[256][68].
// ---------------------------------------------------------------------------
#define QROWS 256
#define SCH   128
#define QP2   52
#define KP2   52
#define VP2   68
#define PP2   68
#define OQ2   0
#define OK2   (QROWS * QP2)            // 13312
#define OV2   (OK2 + SCH * KP2)        // 19968
#define OP2   (OV2 + DKH * VP2)        // 26496
#define SMEM_ATTN_BYTES ((OP2 + QROWS * PP2) * 4)   // 175616

__global__ void __launch_bounds__(256) attn_mma_kernel() {
    extern __shared__ uint32_t sh2[];
    int tid  = threadIdx.x;
    int lane = tid & 31;
    int warp = tid >> 5;
    int g    = lane >> 2;
    int tg   = lane & 3;
    int wq   = warp * 32;

    int t0 = blockIdx.x * QROWS;
    int h  = blockIdx.y;
    int b  = blockIdx.z;

    // ---- Stage Q: direct row copy from g_q16 [b][t][d] ----
    const __half* qb = g_q16 + ((size_t)b * T + t0) * D + h * DKH;
    for (int i = tid; i < 3072; i += 256) {
        int q = i / 12, c = i % 12;
        uint4 v = *(const uint4*)(qb + (size_t)q * D + c * 8);
        *(uint4*)&sh2[OQ2 + q * QP2 + c * 4] = v;
    }

    const __half* kb = g_k16T + (size_t)h * BANK * DKH;
    const __half* vb = g_v16 + (size_t)h * DKH * BANK;

    float o[2][12][4];
    #pragma unroll
    for (int mt = 0; mt < 2; mt++)
        #pragma unroll
        for (int nt = 0; nt < 12; nt++)
            #pragma unroll
            for (int c = 0; c < 4; c++) o[mt][nt][c] = 0.f;
    float lsum[2][2] = {{0.f, 0.f}, {0.f, 0.f}};

    for (int ci = 0; ci < 8; ci++) {
        int s0c = ci * SCH;
        int valid = BANK - s0c; if (valid > SCH) valid = SCH;   // 128 or 104

        __syncthreads();

        // ---- Stage K chunk: [s][dk] row copy, zero rows >= valid ----
        for (int i = tid; i < 1536; i += 256) {
            int row = i / 12, c = i % 12;
            uint4 v = make_uint4(0, 0, 0, 0);
            if (row < valid)
                v = *(const uint4*)(kb + (size_t)(s0c + row) * DKH + c * 8);
            *(uint4*)&sh2[OK2 + row * KP2 + c * 4] = v;
        }
        // ---- Stage V chunk: [dk][s] row copy, zero cols >= valid ----
        for (int i = tid; i < 1536; i += 256) {
            int row = i >> 4, c = i & 15;
            uint4 v = make_uint4(0, 0, 0, 0);
            if (c * 8 + 8 <= valid)
                v = *(const uint4*)(vb + (size_t)row * BANK + s0c + c * 8);
            *(uint4*)&sh2[OV2 + row * VP2 + c * 4] = v;
        }
        __syncthreads();

        // ---- QK + softmax, 32 s-columns per quarter ----
        #pragma unroll
        for (int hf = 0; hf < 4; hf++) {
            float sc[2][4][4];
            #pragma unroll
            for (int mt = 0; mt < 2; mt++)
                #pragma unroll
                for (int nt = 0; nt < 4; nt++)
                    #pragma unroll
                    for (int c = 0; c < 4; c++) sc[mt][nt][c] = 0.f;

            #pragma unroll
            for (int ks = 0; ks < 6; ks++) {
                int kk2 = ks * 8;
                uint32_t a[2][4];
                #pragma unroll
                for (int mt = 0; mt < 2; mt++) {
                    int base = OQ2 + (wq + mt * 16 + g) * QP2 + kk2 + tg;
                    a[mt][0] = sh2[base];
                    a[mt][1] = sh2[base + 8 * QP2];
                    a[mt][2] = sh2[base + 4];
                    a[mt][3] = sh2[base + 8 * QP2 + 4];
                }
                #pragma unroll
                for (int nt = 0; nt < 4; nt++) {
                    int kbse = OK2 + (hf * 32 + nt * 8 + g) * KP2 + kk2 + tg;
                    uint32_t b0 = sh2[kbse];
                    uint32_t b1 = sh2[kbse + 4];
                    mma16(sc[0][nt], a[0][0], a[0][1], a[0][2], a[0][3], b0, b1);
                    mma16(sc[1][nt], a[1][0], a[1][1], a[1][2], a[1][3], b0, b1);
                }
            }

            // exp (no max), mask, store P as fp16
            #pragma unroll
            for (int mt = 0; mt < 2; mt++) {
                int qr = wq + mt * 16;
                #pragma unroll
                for (int nt = 0; nt < 4; nt++) {
                    int scol = hf * 32 + nt * 8 + 2 * tg;
                    int sg = s0c + scol;
                    float p0 = (sg     < BANK) ? ex2f(sc[mt][nt][0]) : 0.f;
                    float p1 = (sg + 1 < BANK) ? ex2f(sc[mt][nt][1]) : 0.f;
                    float p2 = (sg     < BANK) ? ex2f(sc[mt][nt][2]) : 0.f;
                    float p3 = (sg + 1 < BANK) ? ex2f(sc[mt][nt][3]) : 0.f;
                    lsum[mt][0] += p0 + p1;
                    lsum[mt][1] += p2 + p3;
                    int s2 = hf * 16 + nt * 4 + tg;
                    sh2[OP2 + (qr + g)     * PP2 + s2] = h2bits(p0, p1);
                    sh2[OP2 + (qr + g + 8) * PP2 + s2] = h2bits(p2, p3);
                }
            }
        }

        // ---- PV: O[q][dk] += P[q][s] * V[dk][s]  (P warp-private; no sync) ----
        #pragma unroll
        for (int ks = 0; ks < 8; ks++) {
            int sk2 = ks * 8;
            uint32_t a[2][4];
            #pragma unroll
            for (int mt = 0; mt < 2; mt++) {
                int base = OP2 + (wq + mt * 16 + g) * PP2 + sk2 + tg;
                a[mt][0] = sh2[base];
                a[mt][1] = sh2[base + 8 * PP2];
                a[mt][2] = sh2[base + 4];
                a[mt][3] = sh2[base + 8 * PP2 + 4];
            }
            #pragma unroll
            for (int nt = 0; nt < 12; nt++) {
                int vbse = OV2 + (nt * 8 + g) * VP2 + sk2 + tg;
                uint32_t b0 = sh2[vbse];
                uint32_t b1 = sh2[vbse + 4];
                mma16(o[0][nt], a[0][0], a[0][1], a[0][2], a[0][3], b0, b1);
                mma16(o[1][nt], a[1][0], a[1][1], a[1][2], a[1][3], b0, b1);
            }
        }
    }

    // ---- Normalize and write O to g_attn16 [b][t][d] ----
    float inv[2][2];
    #pragma unroll
    for (int mt = 0; mt < 2; mt++)
        #pragma unroll
        for (int j = 0; j < 2; j++) {
            float v = lsum[mt][j];
            v += __shfl_xor_sync(0xFFFFFFFF, v, 1);
            v += __shfl_xor_sync(0xFFFFFFFF, v, 2);
            inv[mt][j] = 1.f / v;
        }

    __half* ob = g_attn16 + ((size_t)b * T + t0) * D + h * DKH;
    #pragma unroll
    for (int mt = 0; mt < 2; mt++) {
        int q_lo = wq + mt * 16 + g;
        int q_hi = q_lo + 8;
        #pragma unroll
        for (int nt = 0; nt < 12; nt++) {
            int dk = nt * 8 + 2 * tg;
            *(uint32_t*)(ob + (size_t)q_lo * D + dk) =
                h2bits(o[mt][nt][0] * inv[mt][0], o[mt][nt][1] * inv[mt][0]);
            *(uint32_t*)(ob + (size_t)q_hi * D + dk) =
                h2bits(o[mt][nt][2] * inv[mt][1], o[mt][nt][3] * inv[mt][1]);
        }
    }
}

// ---------------------------------------------------------------------------
extern "C" void kernel_launch(void* const* d_in, const int* in_sizes, int n_in,
                              void* d_out, int out_size) {
    const float* z  = (const float*)d_in[0];
    const float* mb = (const float*)d_in[1];
    const float* Wq = (const float*)d_in[2];
    const float* bq = (const float*)d_in[3];
    const float* Wk = (const float*)d_in[4];
    const float* bk = (const float*)d_in[5];
    const float* Wv = (const float*)d_in[6];
    const float* bv = (const float*)d_in[7];
    const float* Wo = (const float*)d_in[8];
    const float* bo = (const float*)d_in[9];
    float* out = (float*)d_out;

    const float alpha_q = 1.4426950408889634f / sqrtf(96.0f);

    // 0. Weight prep (fp16 conversion, alpha folded into Wq/bq)
    wprep_kernel<<<2, 256>>>(Wq, bq, Wo, alpha_q);

    // 1. K/V projection (batch-independent) -> fp16
    kv_proj_kernel<<<dim3(4, 24, 2), 256>>>(mb, Wk, bk, Wv, bv);

    // device pointers to prepped weights
    uint32_t *dWq16, *dWo16; float* dbq;
    cudaGetSymbolAddress((void**)&dWq16, g_Wq16);
    cudaGetSymbolAddress((void**)&dWo16, g_Wo16);
    cudaGetSymbolAddress((void**)&dbq,  g_bq);

    // 2. Q projection -> g_q16 [b][t][d] fp16
    cudaFuncSetAttribute(proj16_kernel,
                         cudaFuncAttributeMaxDynamicSharedMemorySize, SMEM_PROJ_BYTES);
    proj16_kernel<<<dim3(32, 1, 16), 256, SMEM_PROJ_BYTES>>>(
        dWq16, dbq, z, 0, nullptr, 1);

    // 3. fp16 mma.sync attention -> g_attn16 [b][t][d]
    cudaFuncSetAttribute(attn_mma_kernel,
                         cudaFuncAttributeMaxDynamicSharedMemorySize, SMEM_ATTN_BYTES);
    attn_mma_kernel<<<dim3(T / QROWS, NH, B), 256, SMEM_ATTN_BYTES>>>();

    // 4. Output projection -> d_out fp32 [b][d][t]
    proj16_kernel<<<dim3(32, 1, 16), 256, SMEM_PROJ_BYTES>>>(
        dWo16, bo, nullptr, 1, out, 0);
}

// round 9
// speedup vs baseline: 1.1116x; 1.1116x over previous
#include <cuda_runtime.h>
#include <cuda_fp16.h>
#include <math.h>
#include <stdint.h>

// Problem constants
#define NH   2
#define DKH  96
#define D    192
#define T    4096
#define B    16
#define BANK 1000

// Scratch (static device allocations)
__device__ __half    g_q16[B * T * D];        // scaled Q, [b][t][d] fp16
__device__ __half    g_attn16[B * T * D];     // attention out pre-Wo, [b][t][d] fp16
__device__ __half    g_k16T[NH * BANK * DKH]; // K, [h][s][dk] fp16
__device__ __half    g_v16[NH * DKH * BANK];  // V, [h][dk][s] fp16
__device__ uint32_t  g_Wq16[D * (D / 2)];     // alpha_q * Wq, [o][k2] h2
__device__ uint32_t  g_Wo16[D * (D / 2)];     // Wo, [o][k2] h2
__device__ float     g_bq[D];                 // alpha_q * bq

__device__ __forceinline__ float ex2f(float x) {
    float r; asm("ex2.approx.ftz.f32 %0, %1;" : "=f"(r) : "f"(x)); return r;
}
__device__ __forceinline__ uint32_t h2bits(float a, float b) {
    __half2 h = __floats2half2_rn(a, b);
    return *(uint32_t*)&h;
}
// m16n8k16 fp16 MMA, f32 accumulate in place.
__device__ __forceinline__ void mma16(float d[4],
                                      uint32_t a0, uint32_t a1, uint32_t a2, uint32_t a3,
                                      uint32_t b0, uint32_t b1) {
    asm volatile("mma.sync.aligned.m16n8k16.row.col.f32.f16.f16.f32 "
                 "{%0,%1,%2,%3}, {%4,%5,%6,%7}, {%8,%9}, {%0,%1,%2,%3};"
                 : "+f"(d[0]), "+f"(d[1]), "+f"(d[2]), "+f"(d[3])
                 : "r"(a0), "r"(a1), "r"(a2), "r"(a3), "r"(b0), "r"(b1));
}

// ---------------------------------------------------------------------------
// Kernel 0: weight prep. Converts Wq (scaled by alpha_q) and Wo to fp16 h2.
// ---------------------------------------------------------------------------
__global__ void wprep_kernel(const float* __restrict__ Wq, const float* __restrict__ bq,
                             const float* __restrict__ Wo, float alpha_q) {
    int which = blockIdx.x;
    const float* W = which ? Wo : Wq;
    uint32_t*  W16 = which ? g_Wo16 : g_Wq16;
    float alpha = which ? 1.0f : alpha_q;
    for (int i = threadIdx.x; i < D * (D / 2); i += 256) {
        int o = i / (D / 2), k2 = i % (D / 2);
        W16[o * (D / 2) + k2] = h2bits(alpha * W[o * D + 2 * k2],
                                       alpha * W[o * D + 2 * k2 + 1]);
    }
    if (which == 0)
        for (int i = threadIdx.x; i < D; i += 256) g_bq[i] = alpha_q * bq[i];
}

// ---------------------------------------------------------------------------
// Kernel 1: K/V projection of memory bank (batch-independent) -> fp16.
// K written transposed [h][s][dk], V as [h][dk][s].
// ---------------------------------------------------------------------------
__global__ void __launch_bounds__(256) kv_proj_kernel(
        const float* __restrict__ mb,
        const float* __restrict__ Wk, const float* __restrict__ bk,
        const float* __restrict__ Wv, const float* __restrict__ bv) {
    __shared__ float wks[4][192];
    __shared__ float wvs[4][192];

    int s   = blockIdx.x * 256 + threadIdx.x;
    int dk0 = blockIdx.y * 4;
    int h   = blockIdx.z;
    int row0 = h * DKH + dk0;

    for (int i = threadIdx.x; i < 4 * 192; i += 256) {
        int j = i / 192, c = i % 192;
        wks[j][c] = Wk[(row0 + j) * D + c];
        wvs[j][c] = Wv[(row0 + j) * D + c];
    }
    __syncthreads();
    if (s >= BANK) return;

    float ak[4] = {0.f, 0.f, 0.f, 0.f};
    float av[4] = {0.f, 0.f, 0.f, 0.f};
    #pragma unroll 4
    for (int c = 0; c < D; c++) {
        float x = mb[c * BANK + s];
        #pragma unroll
        for (int j = 0; j < 4; j++) {
            ak[j] = fmaf(wks[j][c], x, ak[j]);
            av[j] = fmaf(wvs[j][c], x, av[j]);
        }
    }
    __half hk[4];
    #pragma unroll
    for (int j = 0; j < 4; j++) {
        hk[j] = __float2half_rn(ak[j] + bk[row0 + j]);
        g_v16[((size_t)h * DKH + dk0 + j) * BANK + s] = __float2half_rn(av[j] + bv[row0 + j]);
    }
    *(uint2*)&g_k16T[((size_t)h * BANK + s) * DKH + dk0] = *(uint2*)hk;
}

// ---------------------------------------------------------------------------
// Kernel 2/4: channel projection, single-stage full-K fp16 m16n8k16.
// ---------------------------------------------------------------------------
#define PJP2 100
#define SMEM_PROJ_BYTES ((192 * PJP2 + 128 * PJP2) * 4)

__global__ void __launch_bounds__(256) proj16_kernel(
        const uint32_t* __restrict__ W16, const float* __restrict__ bias,
        const float* __restrict__ Xf, int src_half,
        float* __restrict__ Yf, int dst_half) {
    extern __shared__ uint32_t ps[];
    uint32_t* Ws2 = ps;                 // 192*100
    uint32_t* Xs2 = ps + 192 * PJP2;    // 128*100

    int tid  = threadIdx.x;
    int lane = tid & 31;
    int warp = tid >> 5;
    int g    = lane >> 2;
    int tg   = lane & 3;
    int wm   = warp >> 2;
    int wn   = warp & 3;

    int b  = blockIdx.z;
    int t0 = blockIdx.x * 128;
    const float* Xb = Xf + (size_t)b * D * T;
    const __half* Ab = g_attn16 + (size_t)b * T * D;

    for (int i = tid; i < 4608; i += 256) {
        int o = i / 24, c = i % 24;
        uint4 v = *(const uint4*)(W16 + o * 96 + c * 4);
        *(uint4*)&Ws2[o * PJP2 + c * 4] = v;
    }
    if (src_half == 0) {
        for (int i = tid; i < 3072; i += 256) {
            int k2 = i >> 5, t4 = i & 31;
            float4 xa = *(const float4*)(Xb + (size_t)(2 * k2)     * T + t0 + t4 * 4);
            float4 xb = *(const float4*)(Xb + (size_t)(2 * k2 + 1) * T + t0 + t4 * 4);
            Xs2[(t4 * 4 + 0) * PJP2 + k2] = h2bits(xa.x, xb.x);
            Xs2[(t4 * 4 + 1) * PJP2 + k2] = h2bits(xa.y, xb.y);
            Xs2[(t4 * 4 + 2) * PJP2 + k2] = h2bits(xa.z, xb.z);
            Xs2[(t4 * 4 + 3) * PJP2 + k2] = h2bits(xa.w, xb.w);
        }
    } else {
        for (int i = tid; i < 3072; i += 256) {
            int t = i / 24, c = i % 24;
            uint4 v = *(const uint4*)(Ab + (size_t)(t0 + t) * D + c * 8);
            *(uint4*)&Xs2[t * PJP2 + c * 4] = v;
        }
    }
    __syncthreads();

    float acc[4][6][4];
    #pragma unroll
    for (int mt = 0; mt < 4; mt++)
        #pragma unroll
        for (int nt = 0; nt < 6; nt++)
            #pragma unroll
            for (int c = 0; c < 4; c++) acc[mt][nt][c] = 0.f;

    #pragma unroll
    for (int ks = 0; ks < 12; ks++) {
        int kk2 = ks * 8;
        uint32_t bw[6][2];
        #pragma unroll
        for (int nt = 0; nt < 6; nt++) {
            int on = wn * 48 + nt * 8;
            bw[nt][0] = Ws2[(on + g) * PJP2 + kk2 + tg];
            bw[nt][1] = Ws2[(on + g) * PJP2 + kk2 + tg + 4];
        }
        #pragma unroll
        for (int mt = 0; mt < 4; mt++) {
            int tm = wm * 64 + mt * 16;
            uint32_t a0 = Xs2[(tm + g)     * PJP2 + kk2 + tg];
            uint32_t a1 = Xs2[(tm + g + 8) * PJP2 + kk2 + tg];
            uint32_t a2 = Xs2[(tm + g)     * PJP2 + kk2 + tg + 4];
            uint32_t a3 = Xs2[(tm + g + 8) * PJP2 + kk2 + tg + 4];
            #pragma unroll
            for (int nt = 0; nt < 6; nt++)
                mma16(acc[mt][nt], a0, a1, a2, a3, bw[nt][0], bw[nt][1]);
        }
    }

    #pragma unroll
    for (int mt = 0; mt < 4; mt++) {
        int t_lo = wm * 64 + mt * 16 + g;
        int t_hi = t_lo + 8;
        #pragma unroll
        for (int nt = 0; nt < 6; nt++) {
            int o0 = wn * 48 + nt * 8 + 2 * tg;
            float b0v = bias[o0], b1v = bias[o0 + 1];
            float y0 = acc[mt][nt][0] + b0v;
            float y1 = acc[mt][nt][1] + b1v;
            float y2 = acc[mt][nt][2] + b0v;
            float y3 = acc[mt][nt][3] + b1v;
            if (dst_half) {
                *(uint32_t*)&g_q16[((size_t)b * T + t0 + t_lo) * D + o0] = h2bits(y0, y1);
                *(uint32_t*)&g_q16[((size_t)b * T + t0 + t_hi) * D + o0] = h2bits(y2, y3);
            } else {
                Yf[((size_t)b * D + o0)     * T + t0 + t_lo] = y0;
                Yf[((size_t)b * D + o0 + 1) * T + t0 + t_lo] = y1;
                Yf[((size_t)b * D + o0)     * T + t0 + t_hi] = y2;
                Yf[((size_t)b * D + o0 + 1) * T + t0 + t_hi] = y3;
            }
        }
    }
}

// ---------------------------------------------------------------------------
// Kernel 3: fp16 mma.sync attention, no-max softmax. 512 threads / 16 warps.
// Warp (wqi, wsi): wqi in 0..7 owns 32 q rows; wsi in 0..1 owns an s-half for
// QK/softmax (64 of 128 s-cols) and a dk-half for PV (48 of 96 dk-cols).
// l is reduced across the warp pair through SMEM.
// SMEM (h2 words): Qs[256][52], Ks[128][52], Vs[96][68], Ps[256][68], l[2][256].
// ---------------------------------------------------------------------------
#define QROWS 256
#define SCH   128
#define QP2   52
#define KP2   52
#define VP2   68
#define PP2   68
#define OQ2   0
#define OK2   (QROWS * QP2)            // 13312
#define OV2   (OK2 + SCH * KP2)        // 19968
#define OP2   (OV2 + DKH * VP2)        // 26496
#define OL2   (OP2 + QROWS * PP2)      // 43904
#define SMEM_ATTN_BYTES ((OL2 + 2 * QROWS) * 4)   // 177664

__global__ void __launch_bounds__(512, 1) attn_mma_kernel() {
    extern __shared__ uint32_t sh2[];
    float* lsh = (float*)(sh2 + OL2);

    int tid  = threadIdx.x;
    int lane = tid & 31;
    int warp = tid >> 5;
    int g    = lane >> 2;
    int tg   = lane & 3;
    int wqi  = warp >> 1;   // q-group 0..7
    int wsi  = warp & 1;    // s/dk half 0..1
    int wq   = wqi * 32;

    int t0 = blockIdx.x * QROWS;
    int h  = blockIdx.y;
    int b  = blockIdx.z;

    // ---- Stage Q: direct row copy from g_q16 [b][t][d] ----
    const __half* qb = g_q16 + ((size_t)b * T + t0) * D + h * DKH;
    for (int i = tid; i < 3072; i += 512) {
        int q = i / 12, c = i % 12;
        uint4 v = *(const uint4*)(qb + (size_t)q * D + c * 8);
        *(uint4*)&sh2[OQ2 + q * QP2 + c * 4] = v;
    }

    const __half* kb = g_k16T + (size_t)h * BANK * DKH;
    const __half* vb = g_v16 + (size_t)h * DKH * BANK;

    float o[2][6][4];
    #pragma unroll
    for (int mt = 0; mt < 2; mt++)
        #pragma unroll
        for (int nt = 0; nt < 6; nt++)
            #pragma unroll
            for (int c = 0; c < 4; c++) o[mt][nt][c] = 0.f;
    float lsum[2][2] = {{0.f, 0.f}, {0.f, 0.f}};

    for (int ci = 0; ci < 8; ci++) {
        int s0c = ci * SCH;
        int valid = BANK - s0c; if (valid > SCH) valid = SCH;   // 128 or 104

        __syncthreads();   // previous chunk's PV done before restage

        // ---- Stage K chunk: [s][dk] row copy, zero rows >= valid ----
        for (int i = tid; i < 1536; i += 512) {
            int row = i / 12, c = i % 12;
            uint4 v = make_uint4(0, 0, 0, 0);
            if (row < valid)
                v = *(const uint4*)(kb + (size_t)(s0c + row) * DKH + c * 8);
            *(uint4*)&sh2[OK2 + row * KP2 + c * 4] = v;
        }
        // ---- Stage V chunk: [dk][s] row copy, zero cols >= valid ----
        for (int i = tid; i < 1536; i += 512) {
            int row = i >> 4, c = i & 15;
            uint4 v = make_uint4(0, 0, 0, 0);
            if (c * 8 + 8 <= valid)
                v = *(const uint4*)(vb + (size_t)row * BANK + s0c + c * 8);
            *(uint4*)&sh2[OV2 + row * VP2 + c * 4] = v;
        }
        __syncthreads();

        // ---- QK + softmax: this warp's two 32-col quarters ----
        #pragma unroll
        for (int hq = 0; hq < 2; hq++) {
            int hf = 2 * wsi + hq;
            float sc[2][4][4];
            #pragma unroll
            for (int mt = 0; mt < 2; mt++)
                #pragma unroll
                for (int nt = 0; nt < 4; nt++)
                    #pragma unroll
                    for (int c = 0; c < 4; c++) sc[mt][nt][c] = 0.f;

            #pragma unroll
            for (int ks = 0; ks < 6; ks++) {
                int kk2 = ks * 8;
                uint32_t a[2][4];
                #pragma unroll
                for (int mt = 0; mt < 2; mt++) {
                    int base = OQ2 + (wq + mt * 16 + g) * QP2 + kk2 + tg;
                    a[mt][0] = sh2[base];
                    a[mt][1] = sh2[base + 8 * QP2];
                    a[mt][2] = sh2[base + 4];
                    a[mt][3] = sh2[base + 8 * QP2 + 4];
                }
                #pragma unroll
                for (int nt = 0; nt < 4; nt++) {
                    int kbse = OK2 + (hf * 32 + nt * 8 + g) * KP2 + kk2 + tg;
                    uint32_t b0 = sh2[kbse];
                    uint32_t b1 = sh2[kbse + 4];
                    mma16(sc[0][nt], a[0][0], a[0][1], a[0][2], a[0][3], b0, b1);
                    mma16(sc[1][nt], a[1][0], a[1][1], a[1][2], a[1][3], b0, b1);
                }
            }

            // exp (no max), mask, store P as fp16, accumulate partial l
            #pragma unroll
            for (int mt = 0; mt < 2; mt++) {
                int qr = wq + mt * 16;
                #pragma unroll
                for (int nt = 0; nt < 4; nt++) {
                    int scol = hf * 32 + nt * 8 + 2 * tg;
                    int sg = s0c + scol;
                    float p0 = (sg     < BANK) ? ex2f(sc[mt][nt][0]) : 0.f;
                    float p1 = (sg + 1 < BANK) ? ex2f(sc[mt][nt][1]) : 0.f;
                    float p2 = (sg     < BANK) ? ex2f(sc[mt][nt][2]) : 0.f;
                    float p3 = (sg + 1 < BANK) ? ex2f(sc[mt][nt][3]) : 0.f;
                    lsum[mt][0] += p0 + p1;
                    lsum[mt][1] += p2 + p3;
                    int s2 = hf * 16 + nt * 4 + tg;
                    sh2[OP2 + (qr + g)     * PP2 + s2] = h2bits(p0, p1);
                    sh2[OP2 + (qr + g + 8) * PP2 + s2] = h2bits(p2, p3);
                }
            }
        }
        __syncthreads();   // P complete across warp pair before PV

        // ---- PV: O[q][dk_half] += P[q][s] * V[dk][s] over full chunk ----
        #pragma unroll
        for (int ks = 0; ks < 8; ks++) {
            int sk2 = ks * 8;
            uint32_t a[2][4];
            #pragma unroll
            for (int mt = 0; mt < 2; mt++) {
                int base = OP2 + (wq + mt * 16 + g) * PP2 + sk2 + tg;
                a[mt][0] = sh2[base];
                a[mt][1] = sh2[base + 8 * PP2];
                a[mt][2] = sh2[base + 4];
                a[mt][3] = sh2[base + 8 * PP2 + 4];
            }
            #pragma unroll
            for (int nt = 0; nt < 6; nt++) {
                int vbse = OV2 + ((wsi * 6 + nt) * 8 + g) * VP2 + sk2 + tg;
                uint32_t b0 = sh2[vbse];
                uint32_t b1 = sh2[vbse + 4];
                mma16(o[0][nt], a[0][0], a[0][1], a[0][2], a[0][3], b0, b1);
                mma16(o[1][nt], a[1][0], a[1][1], a[1][2], a[1][3], b0, b1);
            }
        }
    }

    // ---- Reduce l within quad, publish per-half, combine across pair ----
    #pragma unroll
    for (int mt = 0; mt < 2; mt++)
        #pragma unroll
        for (int j = 0; j < 2; j++) {
            float v = lsum[mt][j];
            v += __shfl_xor_sync(0xFFFFFFFF, v, 1);
            v += __shfl_xor_sync(0xFFFFFFFF, v, 2);
            lsum[mt][j] = v;
        }
    if (tg == 0) {
        #pragma unroll
        for (int mt = 0; mt < 2; mt++) {
            lsh[wsi * QROWS + wq + mt * 16 + g]     = lsum[mt][0];
            lsh[wsi * QROWS + wq + mt * 16 + g + 8] = lsum[mt][1];
        }
    }
    __syncthreads();

    float inv[2][2];
    #pragma unroll
    for (int mt = 0; mt < 2; mt++) {
        int q_lo = wq + mt * 16 + g;
        inv[mt][0] = 1.f / (lsh[q_lo]     + lsh[QROWS + q_lo]);
        inv[mt][1] = 1.f / (lsh[q_lo + 8] + lsh[QROWS + q_lo + 8]);
    }

    // ---- Write O (warp's dk half) to g_attn16 [b][t][d] ----
    __half* ob = g_attn16 + ((size_t)b * T + t0) * D + h * DKH;
    #pragma unroll
    for (int mt = 0; mt < 2; mt++) {
        int q_lo = wq + mt * 16 + g;
        int q_hi = q_lo + 8;
        #pragma unroll
        for (int nt = 0; nt < 6; nt++) {
            int dk = wsi * 48 + nt * 8 + 2 * tg;
            *(uint32_t*)(ob + (size_t)q_lo * D + dk) =
                h2bits(o[mt][nt][0] * inv[mt][0], o[mt][nt][1] * inv[mt][0]);
            *(uint32_t*)(ob + (size_t)q_hi * D + dk) =
                h2bits(o[mt][nt][2] * inv[mt][1], o[mt][nt][3] * inv[mt][1]);
        }
    }
}

// ---------------------------------------------------------------------------
extern "C" void kernel_launch(void* const* d_in, const int* in_sizes, int n_in,
                              void* d_out, int out_size) {
    const float* z  = (const float*)d_in[0];
    const float* mb = (const float*)d_in[1];
    const float* Wq = (const float*)d_in[2];
    const float* bq = (const float*)d_in[3];
    const float* Wk = (const float*)d_in[4];
    const float* bk = (const float*)d_in[5];
    const float* Wv = (const float*)d_in[6];
    const float* bv = (const float*)d_in[7];
    const float* Wo = (const float*)d_in[8];
    const float* bo = (const float*)d_in[9];
    float* out = (float*)d_out;

    const float alpha_q = 1.4426950408889634f / sqrtf(96.0f);

    // 0. Weight prep (fp16 conversion, alpha folded into Wq/bq)
    wprep_kernel<<<2, 256>>>(Wq, bq, Wo, alpha_q);

    // 1. K/V projection (batch-independent) -> fp16
    kv_proj_kernel<<<dim3(4, 24, 2), 256>>>(mb, Wk, bk, Wv, bv);

    uint32_t *dWq16, *dWo16; float* dbq;
    cudaGetSymbolAddress((void**)&dWq16, g_Wq16);
    cudaGetSymbolAddress((void**)&dWo16, g_Wo16);
    cudaGetSymbolAddress((void**)&dbq,  g_bq);

    // 2. Q projection -> g_q16 [b][t][d] fp16
    cudaFuncSetAttribute(proj16_kernel,
                         cudaFuncAttributeMaxDynamicSharedMemorySize, SMEM_PROJ_BYTES);
    proj16_kernel<<<dim3(32, 1, 16), 256, SMEM_PROJ_BYTES>>>(
        dWq16, dbq, z, 0, nullptr, 1);

    // 3. fp16 mma.sync attention (512 threads) -> g_attn16 [b][t][d]
    cudaFuncSetAttribute(attn_mma_kernel,
                         cudaFuncAttributeMaxDynamicSharedMemorySize, SMEM_ATTN_BYTES);
    attn_mma_kernel<<<dim3(T / QROWS, NH, B), 512, SMEM_ATTN_BYTES>>>();

    // 4. Output projection -> d_out fp32 [b][d][t]
    proj16_kernel<<<dim3(32, 1, 16), 256, SMEM_PROJ_BYTES>>>(
        dWo16, bo, nullptr, 1, out, 0);
}

// round 12
// speedup vs baseline: 1.1593x; 1.0429x over previous
#include <cuda_runtime.h>
#include <cuda_fp16.h>
#include <math.h>
#include <stdint.h>

// Problem constants
#define NH   2
#define DKH  96
#define D    192
#define T    4096
#define B    16
#define BANK 1000

// Scratch (static device allocations)
__device__ __half    g_q16[B * T * D];        // scaled Q, [b][t][d] fp16
__device__ __half    g_attn16[B * T * D];     // attention out pre-Wo, [b][t][d] fp16
__device__ __half    g_k16T[NH * BANK * DKH]; // K, [h][s][dk] fp16
__device__ __half    g_v16[NH * DKH * BANK];  // V, [h][dk][s] fp16
__device__ uint32_t  g_Wq16[D * (D / 2)];     // alpha_q * Wq, [o][k2] h2
__device__ uint32_t  g_Wo16[D * (D / 2)];     // Wo, [o][k2] h2
__device__ float     g_bq[D];                 // alpha_q * bq

__device__ __forceinline__ float ex2f(float x) {
    float r; asm("ex2.approx.ftz.f32 %0, %1;" : "=f"(r) : "f"(x)); return r;
}
__device__ __forceinline__ uint32_t h2bits(float a, float b) {
    __half2 h = __floats2half2_rn(a, b);
    return *(uint32_t*)&h;
}
__device__ __forceinline__ uint32_t smem_addr32(const void* p) {
    return (uint32_t)__cvta_generic_to_shared(p);
}
// m16n8k16 fp16 MMA, f32 accumulate in place.
__device__ __forceinline__ void mma16(float d[4],
                                      const uint32_t a[4],
                                      uint32_t b0, uint32_t b1) {
    asm volatile("mma.sync.aligned.m16n8k16.row.col.f32.f16.f16.f32 "
                 "{%0,%1,%2,%3}, {%4,%5,%6,%7}, {%8,%9}, {%0,%1,%2,%3};"
                 : "+f"(d[0]), "+f"(d[1]), "+f"(d[2]), "+f"(d[3])
                 : "r"(a[0]), "r"(a[1]), "r"(a[2]), "r"(a[3]), "r"(b0), "r"(b1));
}
__device__ __forceinline__ void ldmx4(uint32_t r[4], uint32_t addr) {
    asm volatile("ldmatrix.sync.aligned.m8n8.x4.shared.b16 {%0,%1,%2,%3}, [%4];"
                 : "=r"(r[0]), "=r"(r[1]), "=r"(r[2]), "=r"(r[3]) : "r"(addr));
}
__device__ __forceinline__ void stmx4(uint32_t addr, uint32_t r0, uint32_t r1,
                                      uint32_t r2, uint32_t r3) {
    asm volatile("stmatrix.sync.aligned.m8n8.x4.shared.b16 [%0], {%1,%2,%3,%4};"
                 :: "r"(addr), "r"(r0), "r"(r1), "r"(r2), "r"(r3) : "memory");
}

// ---------------------------------------------------------------------------
// Kernel 0: weight prep. Converts Wq (scaled by alpha_q) and Wo to fp16 h2.
// ---------------------------------------------------------------------------
__global__ void wprep_kernel(const float* __restrict__ Wq, const float* __restrict__ bq,
                             const float* __restrict__ Wo, float alpha_q) {
    int which = blockIdx.x;
    const float* W = which ? Wo : Wq;
    uint32_t*  W16 = which ? g_Wo16 : g_Wq16;
    float alpha = which ? 1.0f : alpha_q;
    for (int i = threadIdx.x; i < D * (D / 2); i += 256) {
        int o = i / (D / 2), k2 = i % (D / 2);
        W16[o * (D / 2) + k2] = h2bits(alpha * W[o * D + 2 * k2],
                                       alpha * W[o * D + 2 * k2 + 1]);
    }
    if (which == 0)
        for (int i = threadIdx.x; i < D; i += 256) g_bq[i] = alpha_q * bq[i];
}

// ---------------------------------------------------------------------------
// Kernel 1: K/V projection of memory bank (batch-independent) -> fp16.
// ---------------------------------------------------------------------------
__global__ void __launch_bounds__(256) kv_proj_kernel(
        const float* __restrict__ mb,
        const float* __restrict__ Wk, const float* __restrict__ bk,
        const float* __restrict__ Wv, const float* __restrict__ bv) {
    __shared__ float wks[4][192];
    __shared__ float wvs[4][192];

    int s   = blockIdx.x * 256 + threadIdx.x;
    int dk0 = blockIdx.y * 4;
    int h   = blockIdx.z;
    int row0 = h * DKH + dk0;

    for (int i = threadIdx.x; i < 4 * 192; i += 256) {
        int j = i / 192, c = i % 192;
        wks[j][c] = Wk[(row0 + j) * D + c];
        wvs[j][c] = Wv[(row0 + j) * D + c];
    }
    __syncthreads();
    if (s >= BANK) return;

    float ak[4] = {0.f, 0.f, 0.f, 0.f};
    float av[4] = {0.f, 0.f, 0.f, 0.f};
    #pragma unroll 4
    for (int c = 0; c < D; c++) {
        float x = mb[c * BANK + s];
        #pragma unroll
        for (int j = 0; j < 4; j++) {
            ak[j] = fmaf(wks[j][c], x, ak[j]);
            av[j] = fmaf(wvs[j][c], x, av[j]);
        }
    }
    __half hk[4];
    #pragma unroll
    for (int j = 0; j < 4; j++) {
        hk[j] = __float2half_rn(ak[j] + bk[row0 + j]);
        g_v16[((size_t)h * DKH + dk0 + j) * BANK + s] = __float2half_rn(av[j] + bv[row0 + j]);
    }
    *(uint2*)&g_k16T[((size_t)h * BANK + s) * DKH + dk0] = *(uint2*)hk;
}

// ---------------------------------------------------------------------------
// Kernel 2/4: channel projection, single-stage full-K fp16 m16n8k16 + ldmatrix.
// SMEM (h2 words, pitch 100 = 25 quads, conflict-free for ldmatrix):
//   Ws2[192][100], Xs2[128][100].
// ---------------------------------------------------------------------------
#define PJP2 100
#define SMEM_PROJ_BYTES ((192 * PJP2 + 128 * PJP2) * 4)

__global__ void __launch_bounds__(256) proj16_kernel(
        const uint32_t* __restrict__ W16, const float* __restrict__ bias,
        const float* __restrict__ Xf, int src_half,
        float* __restrict__ Yf, int dst_half) {
    extern __shared__ uint32_t ps[];
    uint32_t* Ws2 = ps;                 // 192*100
    uint32_t* Xs2 = ps + 192 * PJP2;    // 128*100

    int tid  = threadIdx.x;
    int lane = tid & 31;
    int warp = tid >> 5;
    int g    = lane >> 2;
    int tg   = lane & 3;
    int wm   = warp >> 2;
    int wn   = warp & 3;

    int b  = blockIdx.z;
    int t0 = blockIdx.x * 128;
    const float* Xb = Xf + (size_t)b * D * T;
    const __half* Ab = g_attn16 + (size_t)b * T * D;

    for (int i = tid; i < 4608; i += 256) {
        int o = i / 24, c = i % 24;
        uint4 v = *(const uint4*)(W16 + o * 96 + c * 4);
        *(uint4*)&Ws2[o * PJP2 + c * 4] = v;
    }
    if (src_half == 0) {
        for (int i = tid; i < 3072; i += 256) {
            int k2 = i >> 5, t4 = i & 31;
            float4 xa = *(const float4*)(Xb + (size_t)(2 * k2)     * T + t0 + t4 * 4);
            float4 xb = *(const float4*)(Xb + (size_t)(2 * k2 + 1) * T + t0 + t4 * 4);
            Xs2[(t4 * 4 + 0) * PJP2 + k2] = h2bits(xa.x, xb.x);
            Xs2[(t4 * 4 + 1) * PJP2 + k2] = h2bits(xa.y, xb.y);
            Xs2[(t4 * 4 + 2) * PJP2 + k2] = h2bits(xa.z, xb.z);
            Xs2[(t4 * 4 + 3) * PJP2 + k2] = h2bits(xa.w, xb.w);
        }
    } else {
        for (int i = tid; i < 3072; i += 256) {
            int t = i / 24, c = i % 24;
            uint4 v = *(const uint4*)(Ab + (size_t)(t0 + t) * D + c * 8);
            *(uint4*)&Xs2[t * PJP2 + c * 4] = v;
        }
    }
    __syncthreads();

    // ldmatrix lane-address patterns
    uint32_t sb = smem_addr32(ps);
    int a_row = lane & 15;
    int a_kw  = 4 * ((lane >> 4) & 1);
    int b_row = 8 * ((lane >> 4) & 1) + (lane & 7);
    int b_kw  = 4 * ((lane >> 3) & 1);

    uint32_t xa_addr[4], wb_addr[3];
    #pragma unroll
    for (int mt = 0; mt < 4; mt++)
        xa_addr[mt] = sb + 4 * (192 * PJP2 + (wm * 64 + mt * 16 + a_row) * PJP2 + a_kw);
    #pragma unroll
    for (int np = 0; np < 3; np++)
        wb_addr[np] = sb + 4 * ((wn * 48 + np * 16 + b_row) * PJP2 + b_kw);

    float acc[4][6][4];
    #pragma unroll
    for (int mt = 0; mt < 4; mt++)
        #pragma unroll
        for (int nt = 0; nt < 6; nt++)
            #pragma unroll
            for (int c = 0; c < 4; c++) acc[mt][nt][c] = 0.f;

    #pragma unroll
    for (int ks = 0; ks < 12; ks++) {
        uint32_t koff = ks * 32;   // 16 halves = 8 words = 32 bytes
        uint32_t aX[4][4], bw[3][4];
        #pragma unroll
        for (int mt = 0; mt < 4; mt++) ldmx4(aX[mt], xa_addr[mt] + koff);
        #pragma unroll
        for (int np = 0; np < 3; np++) ldmx4(bw[np], wb_addr[np] + koff);
        #pragma unroll
        for (int mt = 0; mt < 4; mt++)
            #pragma unroll
            for (int np = 0; np < 3; np++) {
                mma16(acc[mt][np * 2],     aX[mt], bw[np][0], bw[np][1]);
                mma16(acc[mt][np * 2 + 1], aX[mt], bw[np][2], bw[np][3]);
            }
    }

    #pragma unroll
    for (int mt = 0; mt < 4; mt++) {
        int t_lo = wm * 64 + mt * 16 + g;
        int t_hi = t_lo + 8;
        #pragma unroll
        for (int nt = 0; nt < 6; nt++) {
            int o0 = wn * 48 + nt * 8 + 2 * tg;
            float b0v = bias[o0], b1v = bias[o0 + 1];
            float y0 = acc[mt][nt][0] + b0v;
            float y1 = acc[mt][nt][1] + b1v;
            float y2 = acc[mt][nt][2] + b0v;
            float y3 = acc[mt][nt][3] + b1v;
            if (dst_half) {
                *(uint32_t*)&g_q16[((size_t)b * T + t0 + t_lo) * D + o0] = h2bits(y0, y1);
                *(uint32_t*)&g_q16[((size_t)b * T + t0 + t_hi) * D + o0] = h2bits(y2, y3);
            } else {
                Yf[((size_t)b * D + o0)     * T + t0 + t_lo] = y0;
                Yf[((size_t)b * D + o0 + 1) * T + t0 + t_lo] = y1;
                Yf[((size_t)b * D + o0)     * T + t0 + t_hi] = y2;
                Yf[((size_t)b * D + o0 + 1) * T + t0 + t_hi] = y3;
            }
        }
    }
}

// ---------------------------------------------------------------------------
// Kernel 3: fp16 mma.sync attention, no-max softmax, ldmatrix/stmatrix.
// 512 threads / 16 warps: wqi (0..7) owns 32 q rows; wsi (0..1) owns an s-half
// in QK/softmax and a dk-half in PV. Pitches 52/68 words (odd quads) are
// ldmatrix-conflict-free.
// ---------------------------------------------------------------------------
#define QROWS 256
#define SCH   128
#define QP2   52
#define KP2   52
#define VP2   68
#define PP2   68
#define OQ2   0
#define OK2   (QROWS * QP2)            // 13312
#define OV2   (OK2 + SCH * KP2)        // 19968
#define OP2   (OV2 + DKH * VP2)        // 26496
#define OL2   (OP2 + QROWS * PP2)      // 43904
#define SMEM_ATTN_BYTES ((OL2 + 2 * QROWS) * 4)   // 177664

__global__ void __launch_bounds__(512, 1) attn_mma_kernel() {
    extern __shared__ uint32_t sh2[];
    float* lsh = (float*)(sh2 + OL2);

    int tid  = threadIdx.x;
    int lane = tid & 31;
    int warp = tid >> 5;
    int g    = lane >> 2;
    int tg   = lane & 3;
    int wqi  = warp >> 1;
    int wsi  = warp & 1;
    int wq   = wqi * 32;

    int t0 = blockIdx.x * QROWS;
    int h  = blockIdx.y;
    int b  = blockIdx.z;

    // ---- Stage Q: direct row copy from g_q16 [b][t][d] ----
    const __half* qb = g_q16 + ((size_t)b * T + t0) * D + h * DKH;
    for (int i = tid; i < 3072; i += 512) {
        int q = i / 12, c = i % 12;
        uint4 v = *(const uint4*)(qb + (size_t)q * D + c * 8);
        *(uint4*)&sh2[OQ2 + q * QP2 + c * 4] = v;
    }

    const __half* kb = g_k16T + (size_t)h * BANK * DKH;
    const __half* vb = g_v16 + (size_t)h * DKH * BANK;

    // ldmatrix / stmatrix lane-address patterns
    uint32_t sb = smem_addr32(sh2);
    int a_row  = lane & 15;
    int a_kw   = 4 * ((lane >> 4) & 1);
    int b_row  = 8 * ((lane >> 4) & 1) + (lane & 7);
    int b_kw   = 4 * ((lane >> 3) & 1);
    int st_row = 8 * ((lane >> 3) & 1) + (lane & 7);
    int st_cw  = 4 * ((lane >> 4) & 1);

    uint32_t qa_addr[2], pa_addr[2], ps_addr[2];
    #pragma unroll
    for (int mt = 0; mt < 2; mt++) {
        qa_addr[mt] = sb + 4 * (OQ2 + (wq + mt * 16 + a_row)  * QP2 + a_kw);
        pa_addr[mt] = sb + 4 * (OP2 + (wq + mt * 16 + a_row)  * PP2 + a_kw);
        ps_addr[mt] = sb + 4 * (OP2 + (wq + mt * 16 + st_row) * PP2 + st_cw);
    }
    uint32_t kb_addr = sb + 4 * (OK2 + b_row * KP2 + b_kw);
    uint32_t vb_addr[3];
    #pragma unroll
    for (int np = 0; np < 3; np++)
        vb_addr[np] = sb + 4 * (OV2 + (wsi * 48 + np * 16 + b_row) * VP2 + b_kw);

    float o[2][6][4];
    #pragma unroll
    for (int mt = 0; mt < 2; mt++)
        #pragma unroll
        for (int nt = 0; nt < 6; nt++)
            #pragma unroll
            for (int c = 0; c < 4; c++) o[mt][nt][c] = 0.f;
    float lsum[2][2] = {{0.f, 0.f}, {0.f, 0.f}};

    for (int ci = 0; ci < 8; ci++) {
        int s0c = ci * SCH;
        int valid = BANK - s0c; if (valid > SCH) valid = SCH;   // 128 or 104

        __syncthreads();

        // ---- Stage K chunk: [s][dk] row copy, zero rows >= valid ----
        for (int i = tid; i < 1536; i += 512) {
            int row = i / 12, c = i % 12;
            uint4 v = make_uint4(0, 0, 0, 0);
            if (row < valid)
                v = *(const uint4*)(kb + (size_t)(s0c + row) * DKH + c * 8);
            *(uint4*)&sh2[OK2 + row * KP2 + c * 4] = v;
        }
        // ---- Stage V chunk: [dk][s] row copy, zero cols >= valid ----
        for (int i = tid; i < 1536; i += 512) {
            int row = i >> 4, c = i & 15;
            uint4 v = make_uint4(0, 0, 0, 0);
            if (c * 8 + 8 <= valid)
                v = *(const uint4*)(vb + (size_t)row * BANK + s0c + c * 8);
            *(uint4*)&sh2[OV2 + row * VP2 + c * 4] = v;
        }
        __syncthreads();

        // ---- QK + softmax: this warp's two 32-col quarters ----
        #pragma unroll
        for (int hq = 0; hq < 2; hq++) {
            int hf = 2 * wsi + hq;
            float sc[2][4][4];
            #pragma unroll
            for (int mt = 0; mt < 2; mt++)
                #pragma unroll
                for (int nt = 0; nt < 4; nt++)
                    #pragma unroll
                    for (int c = 0; c < 4; c++) sc[mt][nt][c] = 0.f;

            #pragma unroll
            for (int ks = 0; ks < 6; ks++) {
                uint32_t koff = ks * 32;
                uint32_t aQ[2][4];
                ldmx4(aQ[0], qa_addr[0] + koff);
                ldmx4(aQ[1], qa_addr[1] + koff);
                #pragma unroll
                for (int np = 0; np < 2; np++) {
                    uint32_t bk4[4];
                    ldmx4(bk4, kb_addr + 4 * (uint32_t)((hf * 32 + np * 16) * KP2) + koff);
                    mma16(sc[0][np * 2],     aQ[0], bk4[0], bk4[1]);
                    mma16(sc[0][np * 2 + 1], aQ[0], bk4[2], bk4[3]);
                    mma16(sc[1][np * 2],     aQ[1], bk4[0], bk4[1]);
                    mma16(sc[1][np * 2 + 1], aQ[1], bk4[2], bk4[3]);
                }
            }

            // exp (no max), mask, accumulate l; store P via stmatrix
            #pragma unroll
            for (int mt = 0; mt < 2; mt++) {
                #pragma unroll
                for (int nt = 0; nt < 4; nt++) {
                    int sg = s0c + hf * 32 + nt * 8 + 2 * tg;
                    float p0 = (sg     < BANK) ? ex2f(sc[mt][nt][0]) : 0.f;
                    float p1 = (sg + 1 < BANK) ? ex2f(sc[mt][nt][1]) : 0.f;
                    float p2 = (sg     < BANK) ? ex2f(sc[mt][nt][2]) : 0.f;
                    float p3 = (sg + 1 < BANK) ? ex2f(sc[mt][nt][3]) : 0.f;
                    lsum[mt][0] += p0 + p1;
                    lsum[mt][1] += p2 + p3;
                    sc[mt][nt][0] = p0; sc[mt][nt][1] = p1;
                    sc[mt][nt][2] = p2; sc[mt][nt][3] = p3;
                }
                #pragma unroll
                for (int np = 0; np < 2; np++) {
                    stmx4(ps_addr[mt] + 4 * (uint32_t)(hf * 16 + np * 8),
                          h2bits(sc[mt][np * 2][0],     sc[mt][np * 2][1]),
                          h2bits(sc[mt][np * 2][2],     sc[mt][np * 2][3]),
                          h2bits(sc[mt][np * 2 + 1][0], sc[mt][np * 2 + 1][1]),
                          h2bits(sc[mt][np * 2 + 1][2], sc[mt][np * 2 + 1][3]));
                }
            }
        }
        __syncthreads();   // P complete across warp pair before PV

        // ---- PV: O[q][dk_half] += P[q][s] * V[dk][s] over full chunk ----
        #pragma unroll
        for (int ks = 0; ks < 8; ks++) {
            uint32_t koff = ks * 32;
            uint32_t aP[2][4];
            ldmx4(aP[0], pa_addr[0] + koff);
            ldmx4(aP[1], pa_addr[1] + koff);
            #pragma unroll
            for (int np = 0; np < 3; np++) {
                uint32_t bv4[4];
                ldmx4(bv4, vb_addr[np] + koff);
                mma16(o[0][np * 2],     aP[0], bv4[0], bv4[1]);
                mma16(o[0][np * 2 + 1], aP[0], bv4[2], bv4[3]);
                mma16(o[1][np * 2],     aP[1], bv4[0], bv4[1]);
                mma16(o[1][np * 2 + 1], aP[1], bv4[2], bv4[3]);
            }
        }
    }

    // ---- Reduce l within quad, publish per-half, combine across pair ----
    #pragma unroll
    for (int mt = 0; mt < 2; mt++)
        #pragma unroll
        for (int j = 0; j < 2; j++) {
            float v = lsum[mt][j];
            v += __shfl_xor_sync(0xFFFFFFFF, v, 1);
            v += __shfl_xor_sync(0xFFFFFFFF, v, 2);
            lsum[mt][j] = v;
        }
    if (tg == 0) {
        #pragma unroll
        for (int mt = 0; mt < 2; mt++) {
            lsh[wsi * QROWS + wq + mt * 16 + g]     = lsum[mt][0];
            lsh[wsi * QROWS + wq + mt * 16 + g + 8] = lsum[mt][1];
        }
    }
    __syncthreads();

    float inv[2][2];
    #pragma unroll
    for (int mt = 0; mt < 2; mt++) {
        int q_lo = wq + mt * 16 + g;
        inv[mt][0] = 1.f / (lsh[q_lo]     + lsh[QROWS + q_lo]);
        inv[mt][1] = 1.f / (lsh[q_lo + 8] + lsh[QROWS + q_lo + 8]);
    }

    // ---- Write O (warp's dk half) to g_attn16 [b][t][d] ----
    __half* ob = g_attn16 + ((size_t)b * T + t0) * D + h * DKH;
    #pragma unroll
    for (int mt = 0; mt < 2; mt++) {
        int q_lo = wq + mt * 16 + g;
        int q_hi = q_lo + 8;
        #pragma unroll
        for (int nt = 0; nt < 6; nt++) {
            int dk = wsi * 48 + nt * 8 + 2 * tg;
            *(uint32_t*)(ob + (size_t)q_lo * D + dk) =
                h2bits(o[mt][nt][0] * inv[mt][0], o[mt][nt][1] * inv[mt][0]);
            *(uint32_t*)(ob + (size_t)q_hi * D + dk) =
                h2bits(o[mt][nt][2] * inv[mt][1], o[mt][nt][3] * inv[mt][1]);
        }
    }
}

// ---------------------------------------------------------------------------
extern "C" void kernel_launch(void* const* d_in, const int* in_sizes, int n_in,
                              void* d_out, int out_size) {
    const float* z  = (const float*)d_in[0];
    const float* mb = (const float*)d_in[1];
    const float* Wq = (const float*)d_in[2];
    const float* bq = (const float*)d_in[3];
    const float* Wk = (const float*)d_in[4];
    const float* bk = (const float*)d_in[5];
    const float* Wv = (const float*)d_in[6];
    const float* bv = (const float*)d_in[7];
    const float* Wo = (const float*)d_in[8];
    const float* bo = (const float*)d_in[9];
    float* out = (float*)d_out;

    const float alpha_q = 1.4426950408889634f / sqrtf(96.0f);

    // 0. Weight prep (fp16 conversion, alpha folded into Wq/bq)
    wprep_kernel<<<2, 256>>>(Wq, bq, Wo, alpha_q);

    // 1. K/V projection (batch-independent) -> fp16
    kv_proj_kernel<<<dim3(4, 24, 2), 256>>>(mb, Wk, bk, Wv, bv);

    uint32_t *dWq16, *dWo16; float* dbq;
    cudaGetSymbolAddress((void**)&dWq16, g_Wq16);
    cudaGetSymbolAddress((void**)&dWo16, g_Wo16);
    cudaGetSymbolAddress((void**)&dbq,  g_bq);

    // 2. Q projection -> g_q16 [b][t][d] fp16
    cudaFuncSetAttribute(proj16_kernel,
                         cudaFuncAttributeMaxDynamicSharedMemorySize, SMEM_PROJ_BYTES);
    proj16_kernel<<<dim3(32, 1, 16), 256, SMEM_PROJ_BYTES>>>(
        dWq16, dbq, z, 0, nullptr, 1);

    // 3. fp16 mma.sync attention (512 threads, ldmatrix) -> g_attn16
    cudaFuncSetAttribute(attn_mma_kernel,
                         cudaFuncAttributeMaxDynamicSharedMemorySize, SMEM_ATTN_BYTES);
    attn_mma_kernel<<<dim3(T / QROWS, NH, B), 512, SMEM_ATTN_BYTES>>>();

    // 4. Output projection -> d_out fp32 [b][d][t]
    proj16_kernel<<<dim3(32, 1, 16), 256, SMEM_PROJ_BYTES>>>(
        dWo16, bo, nullptr, 1, out, 0);
}

// round 13
// speedup vs baseline: 1.2726x; 1.0977x over previous
#include <cuda_runtime.h>
#include <cuda_fp16.h>
#include <math.h>
#include <stdint.h>

// Problem constants
#define NH   2
#define DKH  96
#define D    192
#define T    4096
#define B    16
#define BANK 1000

// Scratch (static device allocations)
__device__ __half    g_q16[B * T * D];        // scaled Q, [b][t][d] fp16
__device__ __half    g_attn16[B * T * D];     // attention out pre-Wo, [b][t][d] fp16
__device__ __half    g_k16T[NH * BANK * DKH]; // K, [h][s][dk] fp16
__device__ __half    g_v16[NH * DKH * BANK];  // V, [h][dk][s] fp16
__device__ uint32_t  g_Wq16[D * (D / 2)];     // alpha_q * Wq, [o][k2] h2
__device__ uint32_t  g_Wo16[D * (D / 2)];     // Wo, [o][k2] h2
__device__ float     g_bq[D];                 // alpha_q * bq

__device__ __forceinline__ float ex2f(float x) {
    float r; asm("ex2.approx.ftz.f32 %0, %1;" : "=f"(r) : "f"(x)); return r;
}
__device__ __forceinline__ uint32_t h2bits(float a, float b) {
    __half2 h = __floats2half2_rn(a, b);
    return *(uint32_t*)&h;
}
__device__ __forceinline__ uint32_t smem_addr32(const void* p) {
    return (uint32_t)__cvta_generic_to_shared(p);
}
__device__ __forceinline__ void mma16(float d[4],
                                      const uint32_t a[4],
                                      uint32_t b0, uint32_t b1) {
    asm volatile("mma.sync.aligned.m16n8k16.row.col.f32.f16.f16.f32 "
                 "{%0,%1,%2,%3}, {%4,%5,%6,%7}, {%8,%9}, {%0,%1,%2,%3};"
                 : "+f"(d[0]), "+f"(d[1]), "+f"(d[2]), "+f"(d[3])
                 : "r"(a[0]), "r"(a[1]), "r"(a[2]), "r"(a[3]), "r"(b0), "r"(b1));
}
__device__ __forceinline__ void ldmx4(uint32_t r[4], uint32_t addr) {
    asm volatile("ldmatrix.sync.aligned.m8n8.x4.shared.b16 {%0,%1,%2,%3}, [%4];"
                 : "=r"(r[0]), "=r"(r[1]), "=r"(r[2]), "=r"(r[3]) : "r"(addr));
}
__device__ __forceinline__ void stmx4(uint32_t addr, uint32_t r0, uint32_t r1,
                                      uint32_t r2, uint32_t r3) {
    asm volatile("stmatrix.sync.aligned.m8n8.x4.shared.b16 [%0], {%1,%2,%3,%4};"
                 :: "r"(addr), "r"(r0), "r"(r1), "r"(r2), "r"(r3) : "memory");
}
__device__ __forceinline__ void cpasync16z(uint32_t dst, const void* src, int srcbytes) {
    asm volatile("cp.async.cg.shared.global [%0], [%1], 16, %2;"
                 :: "r"(dst), "l"(src), "r"(srcbytes) : "memory");
}
__device__ __forceinline__ void cp_commit() {
    asm volatile("cp.async.commit_group;" ::: "memory");
}
__device__ __forceinline__ void cp_wait_all() {
    asm volatile("cp.async.wait_group 0;" ::: "memory");
}

// ---------------------------------------------------------------------------
// Kernel 0: weight prep. Converts Wq (scaled by alpha_q) and Wo to fp16 h2.
// ---------------------------------------------------------------------------
__global__ void wprep_kernel(const float* __restrict__ Wq, const float* __restrict__ bq,
                             const float* __restrict__ Wo, float alpha_q) {
    int which = blockIdx.x;
    const float* W = which ? Wo : Wq;
    uint32_t*  W16 = which ? g_Wo16 : g_Wq16;
    float alpha = which ? 1.0f : alpha_q;
    for (int i = threadIdx.x; i < D * (D / 2); i += 256) {
        int o = i / (D / 2), k2 = i % (D / 2);
        W16[o * (D / 2) + k2] = h2bits(alpha * W[o * D + 2 * k2],
                                       alpha * W[o * D + 2 * k2 + 1]);
    }
    if (which == 0)
        for (int i = threadIdx.x; i < D; i += 256) g_bq[i] = alpha_q * bq[i];
}

// ---------------------------------------------------------------------------
// Kernel 1: K/V projection of memory bank (batch-independent) -> fp16.
// ---------------------------------------------------------------------------
__global__ void __launch_bounds__(256) kv_proj_kernel(
        const float* __restrict__ mb,
        const float* __restrict__ Wk, const float* __restrict__ bk,
        const float* __restrict__ Wv, const float* __restrict__ bv) {
    __shared__ float wks[4][192];
    __shared__ float wvs[4][192];

    int s   = blockIdx.x * 256 + threadIdx.x;
    int dk0 = blockIdx.y * 4;
    int h   = blockIdx.z;
    int row0 = h * DKH + dk0;

    for (int i = threadIdx.x; i < 4 * 192; i += 256) {
        int j = i / 192, c = i % 192;
        wks[j][c] = Wk[(row0 + j) * D + c];
        wvs[j][c] = Wv[(row0 + j) * D + c];
    }
    __syncthreads();
    if (s >= BANK) return;

    float ak[4] = {0.f, 0.f, 0.f, 0.f};
    float av[4] = {0.f, 0.f, 0.f, 0.f};
    #pragma unroll 4
    for (int c = 0; c < D; c++) {
        float x = mb[c * BANK + s];
        #pragma unroll
        for (int j = 0; j < 4; j++) {
            ak[j] = fmaf(wks[j][c], x, ak[j]);
            av[j] = fmaf(wvs[j][c], x, av[j]);
        }
    }
    __half hk[4];
    #pragma unroll
    for (int j = 0; j < 4; j++) {
        hk[j] = __float2half_rn(ak[j] + bk[row0 + j]);
        g_v16[((size_t)h * DKH + dk0 + j) * BANK + s] = __float2half_rn(av[j] + bv[row0 + j]);
    }
    *(uint2*)&g_k16T[((size_t)h * BANK + s) * DKH + dk0] = *(uint2*)hk;
}

// ---------------------------------------------------------------------------
// Kernel 2/4: channel projection, single-stage full-K fp16 m16n8k16 + ldmatrix.
// ---------------------------------------------------------------------------
#define PJP2 100
#define SMEM_PROJ_BYTES ((192 * PJP2 + 128 * PJP2) * 4)

__global__ void __launch_bounds__(256) proj16_kernel(
        const uint32_t* __restrict__ W16, const float* __restrict__ bias,
        const float* __restrict__ Xf, int src_half,
        float* __restrict__ Yf, int dst_half) {
    extern __shared__ uint32_t ps[];
    uint32_t* Ws2 = ps;                 // 192*100
    uint32_t* Xs2 = ps + 192 * PJP2;    // 128*100

    int tid  = threadIdx.x;
    int lane = tid & 31;
    int warp = tid >> 5;
    int g    = lane >> 2;
    int tg   = lane & 3;
    int wm   = warp >> 2;
    int wn   = warp & 3;

    int b  = blockIdx.z;
    int t0 = blockIdx.x * 128;
    const float* Xb = Xf + (size_t)b * D * T;
    const __half* Ab = g_attn16 + (size_t)b * T * D;

    for (int i = tid; i < 4608; i += 256) {
        int o = i / 24, c = i % 24;
        uint4 v = *(const uint4*)(W16 + o * 96 + c * 4);
        *(uint4*)&Ws2[o * PJP2 + c * 4] = v;
    }
    if (src_half == 0) {
        for (int i = tid; i < 3072; i += 256) {
            int k2 = i >> 5, t4 = i & 31;
            float4 xa = *(const float4*)(Xb + (size_t)(2 * k2)     * T + t0 + t4 * 4);
            float4 xb = *(const float4*)(Xb + (size_t)(2 * k2 + 1) * T + t0 + t4 * 4);
            Xs2[(t4 * 4 + 0) * PJP2 + k2] = h2bits(xa.x, xb.x);
            Xs2[(t4 * 4 + 1) * PJP2 + k2] = h2bits(xa.y, xb.y);
            Xs2[(t4 * 4 + 2) * PJP2 + k2] = h2bits(xa.z, xb.z);
            Xs2[(t4 * 4 + 3) * PJP2 + k2] = h2bits(xa.w, xb.w);
        }
    } else {
        for (int i = tid; i < 3072; i += 256) {
            int t = i / 24, c = i % 24;
            uint4 v = *(const uint4*)(Ab + (size_t)(t0 + t) * D + c * 8);
            *(uint4*)&Xs2[t * PJP2 + c * 4] = v;
        }
    }
    __syncthreads();

    uint32_t sb = smem_addr32(ps);
    int a_row = lane & 15;
    int a_kw  = 4 * ((lane >> 4) & 1);
    int b_row = 8 * ((lane >> 4) & 1) + (lane & 7);
    int b_kw  = 4 * ((lane >> 3) & 1);

    uint32_t xa_addr[4], wb_addr[3];
    #pragma unroll
    for (int mt = 0; mt < 4; mt++)
        xa_addr[mt] = sb + 4 * (192 * PJP2 + (wm * 64 + mt * 16 + a_row) * PJP2 + a_kw);
    #pragma unroll
    for (int np = 0; np < 3; np++)
        wb_addr[np] = sb + 4 * ((wn * 48 + np * 16 + b_row) * PJP2 + b_kw);

    float acc[4][6][4];
    #pragma unroll
    for (int mt = 0; mt < 4; mt++)
        #pragma unroll
        for (int nt = 0; nt < 6; nt++)
            #pragma unroll
            for (int c = 0; c < 4; c++) acc[mt][nt][c] = 0.f;

    #pragma unroll
    for (int ks = 0; ks < 12; ks++) {
        uint32_t koff = ks * 32;
        uint32_t aX[4][4], bw[3][4];
        #pragma unroll
        for (int mt = 0; mt < 4; mt++) ldmx4(aX[mt], xa_addr[mt] + koff);
        #pragma unroll
        for (int np = 0; np < 3; np++) ldmx4(bw[np], wb_addr[np] + koff);
        #pragma unroll
        for (int mt = 0; mt < 4; mt++)
            #pragma unroll
            for (int np = 0; np < 3; np++) {
                mma16(acc[mt][np * 2],     aX[mt], bw[np][0], bw[np][1]);
                mma16(acc[mt][np * 2 + 1], aX[mt], bw[np][2], bw[np][3]);
            }
    }

    #pragma unroll
    for (int mt = 0; mt < 4; mt++) {
        int t_lo = wm * 64 + mt * 16 + g;
        int t_hi = t_lo + 8;
        #pragma unroll
        for (int nt = 0; nt < 6; nt++) {
            int o0 = wn * 48 + nt * 8 + 2 * tg;
            float b0v = bias[o0], b1v = bias[o0 + 1];
            float y0 = acc[mt][nt][0] + b0v;
            float y1 = acc[mt][nt][1] + b1v;
            float y2 = acc[mt][nt][2] + b0v;
            float y3 = acc[mt][nt][3] + b1v;
            if (dst_half) {
                *(uint32_t*)&g_q16[((size_t)b * T + t0 + t_lo) * D + o0] = h2bits(y0, y1);
                *(uint32_t*)&g_q16[((size_t)b * T + t0 + t_hi) * D + o0] = h2bits(y2, y3);
            } else {
                Yf[((size_t)b * D + o0)     * T + t0 + t_lo] = y0;
                Yf[((size_t)b * D + o0 + 1) * T + t0 + t_lo] = y1;
                Yf[((size_t)b * D + o0)     * T + t0 + t_hi] = y2;
                Yf[((size_t)b * D + o0 + 1) * T + t0 + t_hi] = y3;
            }
        }
    }
}

// ---------------------------------------------------------------------------
// Kernel 3: fp16 mma.sync attention, no-max softmax, ldmatrix/stmatrix,
// cp.async double-buffered K and V (staging fully overlapped, 2 syncs/chunk).
// 512 threads / 16 warps: wqi (0..7) owns 32 q rows; wsi (0..1) owns an s-half
// in QK/softmax and a dk-half in PV.
// SMEM (h2 words): Q[256][52], K[2][128][52], V[2][96][68], P[256][68], l[512].
// ---------------------------------------------------------------------------
#define QROWS 256
#define SCH   128
#define QP2   52
#define KP2   52
#define VP2   68
#define PP2   68
#define KSZ   (SCH * KP2)              // 6656
#define VSZ   (DKH * VP2)              // 6528
#define OQ2   0
#define OK2   (QROWS * QP2)            // 13312 (buf0); buf1 at +KSZ
#define OV2   (OK2 + 2 * KSZ)          // 26624 (buf0); buf1 at +VSZ
#define OP2   (OV2 + 2 * VSZ)          // 39680
#define OL2   (OP2 + QROWS * PP2)      // 57088
#define SMEM_ATTN_BYTES ((OL2 + 2 * QROWS) * 4)   // 230400

__global__ void __launch_bounds__(512, 1) attn_mma_kernel() {
    extern __shared__ uint32_t sh2[];
    float* lsh = (float*)(sh2 + OL2);

    int tid  = threadIdx.x;
    int lane = tid & 31;
    int warp = tid >> 5;
    int g    = lane >> 2;
    int tg   = lane & 3;
    int wqi  = warp >> 1;
    int wsi  = warp & 1;
    int wq   = wqi * 32;

    int t0 = blockIdx.x * QROWS;
    int h  = blockIdx.y;
    int b  = blockIdx.z;

    uint32_t sb = smem_addr32(sh2);
    const __half* kb = g_k16T + (size_t)h * BANK * DKH;
    const __half* vb = g_v16 + (size_t)h * DKH * BANK;

    // ---- Prefetch K/V for a chunk via cp.async (zero-filled tail) ----
    auto stage_kv = [&](int cin) {
        int s0c2 = cin * SCH;
        int valid2 = BANK - s0c2; if (valid2 > SCH) valid2 = SCH;
        uint32_t kdst = sb + 4u * (OK2 + (cin & 1) * KSZ);
        uint32_t vdst = sb + 4u * (OV2 + (cin & 1) * VSZ);
        #pragma unroll
        for (int it = 0; it < 3; it++) {
            int i = tid + it * 512;
            int row = i / 12, c = i % 12;
            int ok = row < valid2;
            const __half* src = kb + (size_t)(s0c2 + (ok ? row : 0)) * DKH + c * 8;
            cpasync16z(kdst + 4u * (row * KP2 + c * 4), src, ok ? 16 : 0);
        }
        #pragma unroll
        for (int it = 0; it < 3; it++) {
            int i = tid + it * 512;
            int row = i >> 4, c = i & 15;
            int ok = (c * 8 + 8) <= valid2;
            const __half* src = vb + (size_t)row * BANK + s0c2 + (ok ? c * 8 : 0);
            cpasync16z(vdst + 4u * (row * VP2 + c * 4), src, ok ? 16 : 0);
        }
        cp_commit();
    };

    // Prologue: prefetch chunk 0, stage Q (plain loads)
    stage_kv(0);
    const __half* qb = g_q16 + ((size_t)b * T + t0) * D + h * DKH;
    for (int i = tid; i < 3072; i += 512) {
        int q = i / 12, c = i % 12;
        uint4 v = *(const uint4*)(qb + (size_t)q * D + c * 8);
        *(uint4*)&sh2[OQ2 + q * QP2 + c * 4] = v;
    }

    // ldmatrix / stmatrix lane-address patterns
    int a_row  = lane & 15;
    int a_kw   = 4 * ((lane >> 4) & 1);
    int b_row  = 8 * ((lane >> 4) & 1) + (lane & 7);
    int b_kw   = 4 * ((lane >> 3) & 1);
    int st_row = 8 * ((lane >> 3) & 1) + (lane & 7);
    int st_cw  = 4 * ((lane >> 4) & 1);

    uint32_t qa_addr[2], pa_addr[2], ps_addr[2];
    #pragma unroll
    for (int mt = 0; mt < 2; mt++) {
        qa_addr[mt] = sb + 4 * (OQ2 + (wq + mt * 16 + a_row)  * QP2 + a_kw);
        pa_addr[mt] = sb + 4 * (OP2 + (wq + mt * 16 + a_row)  * PP2 + a_kw);
        ps_addr[mt] = sb + 4 * (OP2 + (wq + mt * 16 + st_row) * PP2 + st_cw);
    }
    uint32_t kb_addr0 = sb + 4 * (OK2 + b_row * KP2 + b_kw);
    uint32_t vb_addr0 = sb + 4 * (OV2 + (wsi * 48 + b_row) * VP2 + b_kw);

    float o[2][6][4];
    #pragma unroll
    for (int mt = 0; mt < 2; mt++)
        #pragma unroll
        for (int nt = 0; nt < 6; nt++)
            #pragma unroll
            for (int c = 0; c < 4; c++) o[mt][nt][c] = 0.f;
    float lsum[2][2] = {{0.f, 0.f}, {0.f, 0.f}};

    for (int ci = 0; ci < 8; ci++) {
        int s0c = ci * SCH;
        uint32_t kbuf = kb_addr0 + 4u * ((ci & 1) * KSZ);
        uint32_t vbuf = vb_addr0 + 4u * ((ci & 1) * VSZ);

        cp_wait_all();
        __syncthreads();   // K/V(ci) ready; P(ci-1) consumed; Q visible

        if (ci < 7) stage_kv(ci + 1);

        // ---- QK + softmax: this warp's two 32-col quarters ----
        #pragma unroll
        for (int hq = 0; hq < 2; hq++) {
            int hf = 2 * wsi + hq;
            float sc[2][4][4];
            #pragma unroll
            for (int mt = 0; mt < 2; mt++)
                #pragma unroll
                for (int nt = 0; nt < 4; nt++)
                    #pragma unroll
                    for (int c = 0; c < 4; c++) sc[mt][nt][c] = 0.f;

            #pragma unroll
            for (int ks = 0; ks < 6; ks++) {
                uint32_t koff = ks * 32;
                uint32_t aQ[2][4];
                ldmx4(aQ[0], qa_addr[0] + koff);
                ldmx4(aQ[1], qa_addr[1] + koff);
                #pragma unroll
                for (int np = 0; np < 2; np++) {
                    uint32_t bk4[4];
                    ldmx4(bk4, kbuf + 4 * (uint32_t)((hf * 32 + np * 16) * KP2) + koff);
                    mma16(sc[0][np * 2],     aQ[0], bk4[0], bk4[1]);
                    mma16(sc[0][np * 2 + 1], aQ[0], bk4[2], bk4[3]);
                    mma16(sc[1][np * 2],     aQ[1], bk4[0], bk4[1]);
                    mma16(sc[1][np * 2 + 1], aQ[1], bk4[2], bk4[3]);
                }
            }

            // exp (no max), mask, accumulate l; store P via stmatrix
            #pragma unroll
            for (int mt = 0; mt < 2; mt++) {
                #pragma unroll
                for (int nt = 0; nt < 4; nt++) {
                    int sg = s0c + hf * 32 + nt * 8 + 2 * tg;
                    float p0 = (sg     < BANK) ? ex2f(sc[mt][nt][0]) : 0.f;
                    float p1 = (sg + 1 < BANK) ? ex2f(sc[mt][nt][1]) : 0.f;
                    float p2 = (sg     < BANK) ? ex2f(sc[mt][nt][2]) : 0.f;
                    float p3 = (sg + 1 < BANK) ? ex2f(sc[mt][nt][3]) : 0.f;
                    lsum[mt][0] += p0 + p1;
                    lsum[mt][1] += p2 + p3;
                    sc[mt][nt][0] = p0; sc[mt][nt][1] = p1;
                    sc[mt][nt][2] = p2; sc[mt][nt][3] = p3;
                }
                #pragma unroll
                for (int np = 0; np < 2; np++) {
                    stmx4(ps_addr[mt] + 4 * (uint32_t)(hf * 16 + np * 8),
                          h2bits(sc[mt][np * 2][0],     sc[mt][np * 2][1]),
                          h2bits(sc[mt][np * 2][2],     sc[mt][np * 2][3]),
                          h2bits(sc[mt][np * 2 + 1][0], sc[mt][np * 2 + 1][1]),
                          h2bits(sc[mt][np * 2 + 1][2], sc[mt][np * 2 + 1][3]));
                }
            }
        }
        __syncthreads();   // P complete across warp pair before PV

        // ---- PV: O[q][dk_half] += P[q][s] * V[dk][s] over full chunk ----
        #pragma unroll
        for (int ks = 0; ks < 8; ks++) {
            uint32_t koff = ks * 32;
            uint32_t aP[2][4];
            ldmx4(aP[0], pa_addr[0] + koff);
            ldmx4(aP[1], pa_addr[1] + koff);
            #pragma unroll
            for (int np = 0; np < 3; np++) {
                uint32_t bv4[4];
                ldmx4(bv4, vbuf + 4 * (uint32_t)(np * 16 * VP2) + koff);
                mma16(o[0][np * 2],     aP[0], bv4[0], bv4[1]);
                mma16(o[0][np * 2 + 1], aP[0], bv4[2], bv4[3]);
                mma16(o[1][np * 2],     aP[1], bv4[0], bv4[1]);
                mma16(o[1][np * 2 + 1], aP[1], bv4[2], bv4[3]);
            }
        }
    }

    // ---- Reduce l within quad, publish per-half, combine across pair ----
    #pragma unroll
    for (int mt = 0; mt < 2; mt++)
        #pragma unroll
        for (int j = 0; j < 2; j++) {
            float v = lsum[mt][j];
            v += __shfl_xor_sync(0xFFFFFFFF, v, 1);
            v += __shfl_xor_sync(0xFFFFFFFF, v, 2);
            lsum[mt][j] = v;
        }
    __syncthreads();   // PV(7) done everywhere before reusing lsh region
    if (tg == 0) {
        #pragma unroll
        for (int mt = 0; mt < 2; mt++) {
            lsh[wsi * QROWS + wq + mt * 16 + g]     = lsum[mt][0];
            lsh[wsi * QROWS + wq + mt * 16 + g + 8] = lsum[mt][1];
        }
    }
    __syncthreads();

    float inv[2][2];
    #pragma unroll
    for (int mt = 0; mt < 2; mt++) {
        int q_lo = wq + mt * 16 + g;
        inv[mt][0] = 1.f / (lsh[q_lo]     + lsh[QROWS + q_lo]);
        inv[mt][1] = 1.f / (lsh[q_lo + 8] + lsh[QROWS + q_lo + 8]);
    }

    // ---- Write O (warp's dk half) to g_attn16 [b][t][d] ----
    __half* ob = g_attn16 + ((size_t)b * T + t0) * D + h * DKH;
    #pragma unroll
    for (int mt = 0; mt < 2; mt++) {
        int q_lo = wq + mt * 16 + g;
        int q_hi = q_lo + 8;
        #pragma unroll
        for (int nt = 0; nt < 6; nt++) {
            int dk = wsi * 48 + nt * 8 + 2 * tg;
            *(uint32_t*)(ob + (size_t)q_lo * D + dk) =
                h2bits(o[mt][nt][0] * inv[mt][0], o[mt][nt][1] * inv[mt][0]);
            *(uint32_t*)(ob + (size_t)q_hi * D + dk) =
                h2bits(o[mt][nt][2] * inv[mt][1], o[mt][nt][3] * inv[mt][1]);
        }
    }
}

// ---------------------------------------------------------------------------
extern "C" void kernel_launch(void* const* d_in, const int* in_sizes, int n_in,
                              void* d_out, int out_size) {
    const float* z  = (const float*)d_in[0];
    const float* mb = (const float*)d_in[1];
    const float* Wq = (const float*)d_in[2];
    const float* bq = (const float*)d_in[3];
    const float* Wk = (const float*)d_in[4];
    const float* bk = (const float*)d_in[5];
    const float* Wv = (const float*)d_in[6];
    const float* bv = (const float*)d_in[7];
    const float* Wo = (const float*)d_in[8];
    const float* bo = (const float*)d_in[9];
    float* out = (float*)d_out;

    const float alpha_q = 1.4426950408889634f / sqrtf(96.0f);

    // 0. Weight prep (fp16 conversion, alpha folded into Wq/bq)
    wprep_kernel<<<2, 256>>>(Wq, bq, Wo, alpha_q);

    // 1. K/V projection (batch-independent) -> fp16
    kv_proj_kernel<<<dim3(4, 24, 2), 256>>>(mb, Wk, bk, Wv, bv);

    uint32_t *dWq16, *dWo16; float* dbq;
    cudaGetSymbolAddress((void**)&dWq16, g_Wq16);
    cudaGetSymbolAddress((void**)&dWo16, g_Wo16);
    cudaGetSymbolAddress((void**)&dbq,  g_bq);

    // 2. Q projection -> g_q16 [b][t][d] fp16
    cudaFuncSetAttribute(proj16_kernel,
                         cudaFuncAttributeMaxDynamicSharedMemorySize, SMEM_PROJ_BYTES);
    proj16_kernel<<<dim3(32, 1, 16), 256, SMEM_PROJ_BYTES>>>(
        dWq16, dbq, z, 0, nullptr, 1);

    // 3. fp16 mma.sync attention (cp.async pipelined) -> g_attn16
    cudaFuncSetAttribute(attn_mma_kernel,
                         cudaFuncAttributeMaxDynamicSharedMemorySize, SMEM_ATTN_BYTES);
    attn_mma_kernel<<<dim3(T / QROWS, NH, B), 512, SMEM_ATTN_BYTES>>>();

    // 4. Output projection -> d_out fp32 [b][d][t]
    proj16_kernel<<<dim3(32, 1, 16), 256, SMEM_PROJ_BYTES>>>(
        dWo16, bo, nullptr, 1, out, 0);
}

// round 14
// speedup vs baseline: 1.4758x; 1.1596x over previous
#include <cuda_runtime.h>
#include <cuda_fp16.h>
#include <math.h>
#include <stdint.h>

// Problem constants
#define NH   2
#define DKH  96
#define D    192
#define T    4096
#define B    16
#define BANK 1000

// Scratch (static device allocations)
__device__ __half    g_q16[B * T * D];        // scaled Q, [b][t][d] fp16
__device__ __half    g_attn16[B * T * D];     // attention out pre-Wo, [b][t][d] fp16
__device__ __half    g_k16T[NH * BANK * DKH]; // K, [h][s][dk] fp16
__device__ __half    g_v16[NH * DKH * BANK];  // V, [h][dk][s] fp16
__device__ uint32_t  g_Wq16[D * (D / 2)];     // alpha_q * Wq, [o][k2] h2
__device__ uint32_t  g_Wo16[D * (D / 2)];     // Wo, [o][k2] h2
__device__ float     g_bq[D];                 // alpha_q * bq

__device__ __forceinline__ float ex2f(float x) {
    float r; asm("ex2.approx.ftz.f32 %0, %1;" : "=f"(r) : "f"(x)); return r;
}
__device__ __forceinline__ uint32_t h2bits(float a, float b) {
    __half2 h = __floats2half2_rn(a, b);
    return *(uint32_t*)&h;
}
__device__ __forceinline__ uint32_t smem_addr32(const void* p) {
    return (uint32_t)__cvta_generic_to_shared(p);
}
__device__ __forceinline__ void mma16(float d[4],
                                      const uint32_t a[4],
                                      uint32_t b0, uint32_t b1) {
    asm volatile("mma.sync.aligned.m16n8k16.row.col.f32.f16.f16.f32 "
                 "{%0,%1,%2,%3}, {%4,%5,%6,%7}, {%8,%9}, {%0,%1,%2,%3};"
                 : "+f"(d[0]), "+f"(d[1]), "+f"(d[2]), "+f"(d[3])
                 : "r"(a[0]), "r"(a[1]), "r"(a[2]), "r"(a[3]), "r"(b0), "r"(b1));
}
__device__ __forceinline__ void ldmx4(uint32_t r[4], uint32_t addr) {
    asm volatile("ldmatrix.sync.aligned.m8n8.x4.shared.b16 {%0,%1,%2,%3}, [%4];"
                 : "=r"(r[0]), "=r"(r[1]), "=r"(r[2]), "=r"(r[3]) : "r"(addr));
}
__device__ __forceinline__ void stmx4(uint32_t addr, uint32_t r0, uint32_t r1,
                                      uint32_t r2, uint32_t r3) {
    asm volatile("stmatrix.sync.aligned.m8n8.x4.shared.b16 [%0], {%1,%2,%3,%4};"
                 :: "r"(addr), "r"(r0), "r"(r1), "r"(r2), "r"(r3) : "memory");
}
__device__ __forceinline__ void cpasync16z(uint32_t dst, const void* src, int srcbytes) {
    asm volatile("cp.async.cg.shared.global [%0], [%1], 16, %2;"
                 :: "r"(dst), "l"(src), "r"(srcbytes) : "memory");
}
__device__ __forceinline__ void cpasync16(uint32_t dst, const void* src) {
    asm volatile("cp.async.cg.shared.global [%0], [%1], 16;"
                 :: "r"(dst), "l"(src) : "memory");
}
__device__ __forceinline__ void cp_commit() {
    asm volatile("cp.async.commit_group;" ::: "memory");
}
__device__ __forceinline__ void cp_wait_all() {
    asm volatile("cp.async.wait_group 0;" ::: "memory");
}

// ---------------------------------------------------------------------------
// Kernel 0: weight prep. Converts Wq (scaled by alpha_q) and Wo to fp16 h2.
// ---------------------------------------------------------------------------
__global__ void wprep_kernel(const float* __restrict__ Wq, const float* __restrict__ bq,
                             const float* __restrict__ Wo, float alpha_q) {
    int which = blockIdx.x;
    const float* W = which ? Wo : Wq;
    uint32_t*  W16 = which ? g_Wo16 : g_Wq16;
    float alpha = which ? 1.0f : alpha_q;
    for (int i = threadIdx.x; i < D * (D / 2); i += 256) {
        int o = i / (D / 2), k2 = i % (D / 2);
        W16[o * (D / 2) + k2] = h2bits(alpha * W[o * D + 2 * k2],
                                       alpha * W[o * D + 2 * k2 + 1]);
    }
    if (which == 0)
        for (int i = threadIdx.x; i < D; i += 256) g_bq[i] = alpha_q * bq[i];
}

// ---------------------------------------------------------------------------
// Kernel 1: K/V projection of memory bank (batch-independent) -> fp16.
// ---------------------------------------------------------------------------
__global__ void __launch_bounds__(256) kv_proj_kernel(
        const float* __restrict__ mb,
        const float* __restrict__ Wk, const float* __restrict__ bk,
        const float* __restrict__ Wv, const float* __restrict__ bv) {
    __shared__ float wks[4][192];
    __shared__ float wvs[4][192];

    int s   = blockIdx.x * 256 + threadIdx.x;
    int dk0 = blockIdx.y * 4;
    int h   = blockIdx.z;
    int row0 = h * DKH + dk0;

    for (int i = threadIdx.x; i < 4 * 192; i += 256) {
        int j = i / 192, c = i % 192;
        wks[j][c] = Wk[(row0 + j) * D + c];
        wvs[j][c] = Wv[(row0 + j) * D + c];
    }
    __syncthreads();
    if (s >= BANK) return;

    float ak[4] = {0.f, 0.f, 0.f, 0.f};
    float av[4] = {0.f, 0.f, 0.f, 0.f};
    #pragma unroll 4
    for (int c = 0; c < D; c++) {
        float x = mb[c * BANK + s];
        #pragma unroll
        for (int j = 0; j < 4; j++) {
            ak[j] = fmaf(wks[j][c], x, ak[j]);
            av[j] = fmaf(wvs[j][c], x, av[j]);
        }
    }
    __half hk[4];
    #pragma unroll
    for (int j = 0; j < 4; j++) {
        hk[j] = __float2half_rn(ak[j] + bk[row0 + j]);
        g_v16[((size_t)h * DKH + dk0 + j) * BANK + s] = __float2half_rn(av[j] + bv[row0 + j]);
    }
    *(uint2*)&g_k16T[((size_t)h * BANK + s) * DKH + dk0] = *(uint2*)hk;
}

// ---------------------------------------------------------------------------
// Kernel 2/4: channel projection, fp16 m16n8k16 + ldmatrix, 512 threads.
// Warps 4m x 4n: each warp 2 m16 (t) x 6 n8 (o). cp.async staging for fp16
// sources; coalesced fp32 epilogue through SMEM for the [o][t] output.
// SMEM: Ws2[192][100] + Xs2[128][100] words (128000 B); fbuf reuses region.
// grid (32, 1, 16)
// ---------------------------------------------------------------------------
#define PJP2 100
#define FBP  132
#define SMEM_PROJ_BYTES ((192 * PJP2 + 128 * PJP2) * 4)

__global__ void __launch_bounds__(512) proj16_kernel(
        const uint32_t* __restrict__ W16, const float* __restrict__ bias,
        const float* __restrict__ Xf, int src_half,
        float* __restrict__ Yf, int dst_half) {
    extern __shared__ uint32_t ps[];
    uint32_t* Ws2 = ps;                 // 192*100 words
    uint32_t* Xs2 = ps + 192 * PJP2;    // 128*100 words
    float*    fbuf = (float*)ps;        // epilogue: [192][FBP] floats (101376 B)

    int tid  = threadIdx.x;
    int lane = tid & 31;
    int warp = tid >> 5;
    int g    = lane >> 2;
    int tg   = lane & 3;
    int wm   = warp >> 2;   // t: 32 each (0..3)
    int wn   = warp & 3;    // o: 48 each

    int b  = blockIdx.z;
    int t0 = blockIdx.x * 128;
    const float* Xb = Xf + (size_t)b * D * T;
    const __half* Ab = g_attn16 + (size_t)b * T * D;

    uint32_t sb = smem_addr32(ps);

    // ---- Stage W via cp.async: 4608 uint4, 9 per thread ----
    #pragma unroll
    for (int it = 0; it < 9; it++) {
        int i = tid + it * 512;
        int o = i / 24, c = i % 24;
        cpasync16(sb + 4u * (o * PJP2 + c * 4), W16 + o * 96 + c * 4);
    }
    // ---- Stage X ----
    if (src_half == 0) {
        // fp32 z [d][t]: transpose-convert to [t][k2] (plain loads)
        #pragma unroll
        for (int it = 0; it < 6; it++) {
            int i = tid + it * 512;
            int k2 = i >> 5, t4 = i & 31;
            float4 xa = *(const float4*)(Xb + (size_t)(2 * k2)     * T + t0 + t4 * 4);
            float4 xb = *(const float4*)(Xb + (size_t)(2 * k2 + 1) * T + t0 + t4 * 4);
            Xs2[(t4 * 4 + 0) * PJP2 + k2] = h2bits(xa.x, xb.x);
            Xs2[(t4 * 4 + 1) * PJP2 + k2] = h2bits(xa.y, xb.y);
            Xs2[(t4 * 4 + 2) * PJP2 + k2] = h2bits(xa.z, xb.z);
            Xs2[(t4 * 4 + 3) * PJP2 + k2] = h2bits(xa.w, xb.w);
        }
    } else {
        // fp16 attn [t][d]: cp.async row copies, 6 per thread
        #pragma unroll
        for (int it = 0; it < 6; it++) {
            int i = tid + it * 512;
            int t = i / 24, c = i % 24;
            cpasync16(sb + 4u * (192 * PJP2 + t * PJP2 + c * 4),
                      Ab + (size_t)(t0 + t) * D + c * 8);
        }
    }
    cp_commit();
    cp_wait_all();
    __syncthreads();

    // ldmatrix lane-address patterns
    int a_row = lane & 15;
    int a_kw  = 4 * ((lane >> 4) & 1);
    int b_row = 8 * ((lane >> 4) & 1) + (lane & 7);
    int b_kw  = 4 * ((lane >> 3) & 1);

    uint32_t xa_addr[2], wb_addr[3];
    #pragma unroll
    for (int mt = 0; mt < 2; mt++)
        xa_addr[mt] = sb + 4 * (192 * PJP2 + (wm * 32 + mt * 16 + a_row) * PJP2 + a_kw);
    #pragma unroll
    for (int np = 0; np < 3; np++)
        wb_addr[np] = sb + 4 * ((wn * 48 + np * 16 + b_row) * PJP2 + b_kw);

    float acc[2][6][4];
    #pragma unroll
    for (int mt = 0; mt < 2; mt++)
        #pragma unroll
        for (int nt = 0; nt < 6; nt++)
            #pragma unroll
            for (int c = 0; c < 4; c++) acc[mt][nt][c] = 0.f;

    #pragma unroll
    for (int ks = 0; ks < 12; ks++) {
        uint32_t koff = ks * 32;
        uint32_t aX[2][4], bw[3][4];
        #pragma unroll
        for (int mt = 0; mt < 2; mt++) ldmx4(aX[mt], xa_addr[mt] + koff);
        #pragma unroll
        for (int np = 0; np < 3; np++) ldmx4(bw[np], wb_addr[np] + koff);
        #pragma unroll
        for (int mt = 0; mt < 2; mt++)
            #pragma unroll
            for (int np = 0; np < 3; np++) {
                mma16(acc[mt][np * 2],     aX[mt], bw[np][0], bw[np][1]);
                mma16(acc[mt][np * 2 + 1], aX[mt], bw[np][2], bw[np][3]);
            }
    }

    if (dst_half) {
        // fp16 [t][d] output: direct h2 stores
        #pragma unroll
        for (int mt = 0; mt < 2; mt++) {
            int t_lo = wm * 32 + mt * 16 + g;
            int t_hi = t_lo + 8;
            #pragma unroll
            for (int nt = 0; nt < 6; nt++) {
                int o0 = wn * 48 + nt * 8 + 2 * tg;
                float b0v = bias[o0], b1v = bias[o0 + 1];
                *(uint32_t*)&g_q16[((size_t)b * T + t0 + t_lo) * D + o0] =
                    h2bits(acc[mt][nt][0] + b0v, acc[mt][nt][1] + b1v);
                *(uint32_t*)&g_q16[((size_t)b * T + t0 + t_hi) * D + o0] =
                    h2bits(acc[mt][nt][2] + b0v, acc[mt][nt][3] + b1v);
            }
        }
    } else {
        // fp32 [o][t] output: transpose through SMEM, coalesced float4 writes
        __syncthreads();   // all ldmatrix reads done before fbuf overwrite
        #pragma unroll
        for (int mt = 0; mt < 2; mt++) {
            int t_lo = wm * 32 + mt * 16 + g;
            int t_hi = t_lo + 8;
            #pragma unroll
            for (int nt = 0; nt < 6; nt++) {
                int o0 = wn * 48 + nt * 8 + 2 * tg;
                float b0v = bias[o0], b1v = bias[o0 + 1];
                fbuf[(o0)     * FBP + t_lo] = acc[mt][nt][0] + b0v;
                fbuf[(o0 + 1) * FBP + t_lo] = acc[mt][nt][1] + b1v;
                fbuf[(o0)     * FBP + t_hi] = acc[mt][nt][2] + b0v;
                fbuf[(o0 + 1) * FBP + t_hi] = acc[mt][nt][3] + b1v;
            }
        }
        __syncthreads();
        #pragma unroll
        for (int it = 0; it < 12; it++) {
            int i = tid + it * 512;
            int o = i >> 5, t4 = i & 31;
            float4 v = *(float4*)&fbuf[o * FBP + t4 * 4];
            *(float4*)(Yf + ((size_t)b * D + o) * T + t0 + t4 * 4) = v;
        }
    }
}

// ---------------------------------------------------------------------------
// Kernel 3: fp16 mma.sync attention, no-max softmax, ldmatrix/stmatrix,
// cp.async double-buffered K and V. (unchanged from R13)
// ---------------------------------------------------------------------------
#define QROWS 256
#define SCH   128
#define QP2   52
#define KP2   52
#define VP2   68
#define PP2   68
#define KSZ   (SCH * KP2)              // 6656
#define VSZ   (DKH * VP2)              // 6528
#define OQ2   0
#define OK2   (QROWS * QP2)            // 13312 (buf0); buf1 at +KSZ
#define OV2   (OK2 + 2 * KSZ)          // 26624 (buf0); buf1 at +VSZ
#define OP2   (OV2 + 2 * VSZ)          // 39680
#define OL2   (OP2 + QROWS * PP2)      // 57088
#define SMEM_ATTN_BYTES ((OL2 + 2 * QROWS) * 4)   // 230400

__global__ void __launch_bounds__(512, 1) attn_mma_kernel() {
    extern __shared__ uint32_t sh2[];
    float* lsh = (float*)(sh2 + OL2);

    int tid  = threadIdx.x;
    int lane = tid & 31;
    int warp = tid >> 5;
    int g    = lane >> 2;
    int tg   = lane & 3;
    int wqi  = warp >> 1;
    int wsi  = warp & 1;
    int wq   = wqi * 32;

    int t0 = blockIdx.x * QROWS;
    int h  = blockIdx.y;
    int b  = blockIdx.z;

    uint32_t sb = smem_addr32(sh2);
    const __half* kb = g_k16T + (size_t)h * BANK * DKH;
    const __half* vb = g_v16 + (size_t)h * DKH * BANK;

    auto stage_kv = [&](int cin) {
        int s0c2 = cin * SCH;
        int valid2 = BANK - s0c2; if (valid2 > SCH) valid2 = SCH;
        uint32_t kdst = sb + 4u * (OK2 + (cin & 1) * KSZ);
        uint32_t vdst = sb + 4u * (OV2 + (cin & 1) * VSZ);
        #pragma unroll
        for (int it = 0; it < 3; it++) {
            int i = tid + it * 512;
            int row = i / 12, c = i % 12;
            int ok = row < valid2;
            const __half* src = kb + (size_t)(s0c2 + (ok ? row : 0)) * DKH + c * 8;
            cpasync16z(kdst + 4u * (row * KP2 + c * 4), src, ok ? 16 : 0);
        }
        #pragma unroll
        for (int it = 0; it < 3; it++) {
            int i = tid + it * 512;
            int row = i >> 4, c = i & 15;
            int ok = (c * 8 + 8) <= valid2;
            const __half* src = vb + (size_t)row * BANK + s0c2 + (ok ? c * 8 : 0);
            cpasync16z(vdst + 4u * (row * VP2 + c * 4), src, ok ? 16 : 0);
        }
        cp_commit();
    };

    stage_kv(0);
    const __half* qb = g_q16 + ((size_t)b * T + t0) * D + h * DKH;
    for (int i = tid; i < 3072; i += 512) {
        int q = i / 12, c = i % 12;
        uint4 v = *(const uint4*)(qb + (size_t)q * D + c * 8);
        *(uint4*)&sh2[OQ2 + q * QP2 + c * 4] = v;
    }

    int a_row  = lane & 15;
    int a_kw   = 4 * ((lane >> 4) & 1);
    int b_row  = 8 * ((lane >> 4) & 1) + (lane & 7);
    int b_kw   = 4 * ((lane >> 3) & 1);
    int st_row = 8 * ((lane >> 3) & 1) + (lane & 7);
    int st_cw  = 4 * ((lane >> 4) & 1);

    uint32_t qa_addr[2], pa_addr[2], ps_addr[2];
    #pragma unroll
    for (int mt = 0; mt < 2; mt++) {
        qa_addr[mt] = sb + 4 * (OQ2 + (wq + mt * 16 + a_row)  * QP2 + a_kw);
        pa_addr[mt] = sb + 4 * (OP2 + (wq + mt * 16 + a_row)  * PP2 + a_kw);
        ps_addr[mt] = sb + 4 * (OP2 + (wq + mt * 16 + st_row) * PP2 + st_cw);
    }
    uint32_t kb_addr0 = sb + 4 * (OK2 + b_row * KP2 + b_kw);
    uint32_t vb_addr0 = sb + 4 * (OV2 + (wsi * 48 + b_row) * VP2 + b_kw);

    float o[2][6][4];
    #pragma unroll
    for (int mt = 0; mt < 2; mt++)
        #pragma unroll
        for (int nt = 0; nt < 6; nt++)
            #pragma unroll
            for (int c = 0; c < 4; c++) o[mt][nt][c] = 0.f;
    float lsum[2][2] = {{0.f, 0.f}, {0.f, 0.f}};

    for (int ci = 0; ci < 8; ci++) {
        int s0c = ci * SCH;
        uint32_t kbuf = kb_addr0 + 4u * ((ci & 1) * KSZ);
        uint32_t vbuf = vb_addr0 + 4u * ((ci & 1) * VSZ);

        cp_wait_all();
        __syncthreads();

        if (ci < 7) stage_kv(ci + 1);

        #pragma unroll
        for (int hq = 0; hq < 2; hq++) {
            int hf = 2 * wsi + hq;
            float sc[2][4][4];
            #pragma unroll
            for (int mt = 0; mt < 2; mt++)
                #pragma unroll
                for (int nt = 0; nt < 4; nt++)
                    #pragma unroll
                    for (int c = 0; c < 4; c++) sc[mt][nt][c] = 0.f;

            #pragma unroll
            for (int ks = 0; ks < 6; ks++) {
                uint32_t koff = ks * 32;
                uint32_t aQ[2][4];
                ldmx4(aQ[0], qa_addr[0] + koff);
                ldmx4(aQ[1], qa_addr[1] + koff);
                #pragma unroll
                for (int np = 0; np < 2; np++) {
                    uint32_t bk4[4];
                    ldmx4(bk4, kbuf + 4 * (uint32_t)((hf * 32 + np * 16) * KP2) + koff);
                    mma16(sc[0][np * 2],     aQ[0], bk4[0], bk4[1]);
                    mma16(sc[0][np * 2 + 1], aQ[0], bk4[2], bk4[3]);
                    mma16(sc[1][np * 2],     aQ[1], bk4[0], bk4[1]);
                    mma16(sc[1][np * 2 + 1], aQ[1], bk4[2], bk4[3]);
                }
            }

            #pragma unroll
            for (int mt = 0; mt < 2; mt++) {
                #pragma unroll
                for (int nt = 0; nt < 4; nt++) {
                    int sg = s0c + hf * 32 + nt * 8 + 2 * tg;
                    float p0 = (sg     < BANK) ? ex2f(sc[mt][nt][0]) : 0.f;
                    float p1 = (sg + 1 < BANK) ? ex2f(sc[mt][nt][1]) : 0.f;
                    float p2 = (sg     < BANK) ? ex2f(sc[mt][nt][2]) : 0.f;
                    float p3 = (sg + 1 < BANK) ? ex2f(sc[mt][nt][3]) : 0.f;
                    lsum[mt][0] += p0 + p1;
                    lsum[mt][1] += p2 + p3;
                    sc[mt][nt][0] = p0; sc[mt][nt][1] = p1;
                    sc[mt][nt][2] = p2; sc[mt][nt][3] = p3;
                }
                #pragma unroll
                for (int np = 0; np < 2; np++) {
                    stmx4(ps_addr[mt] + 4 * (uint32_t)(hf * 16 + np * 8),
                          h2bits(sc[mt][np * 2][0],     sc[mt][np * 2][1]),
                          h2bits(sc[mt][np * 2][2],     sc[mt][np * 2][3]),
                          h2bits(sc[mt][np * 2 + 1][0], sc[mt][np * 2 + 1][1]),
                          h2bits(sc[mt][np * 2 + 1][2], sc[mt][np * 2 + 1][3]));
                }
            }
        }
        __syncthreads();

        #pragma unroll
        for (int ks = 0; ks < 8; ks++) {
            uint32_t koff = ks * 32;
            uint32_t aP[2][4];
            ldmx4(aP[0], pa_addr[0] + koff);
            ldmx4(aP[1], pa_addr[1] + koff);
            #pragma unroll
            for (int np = 0; np < 3; np++) {
                uint32_t bv4[4];
                ldmx4(bv4, vbuf + 4 * (uint32_t)(np * 16 * VP2) + koff);
                mma16(o[0][np * 2],     aP[0], bv4[0], bv4[1]);
                mma16(o[0][np * 2 + 1], aP[0], bv4[2], bv4[3]);
                mma16(o[1][np * 2],     aP[1], bv4[0], bv4[1]);
                mma16(o[1][np * 2 + 1], aP[1], bv4[2], bv4[3]);
            }
        }
    }

    #pragma unroll
    for (int mt = 0; mt < 2; mt++)
        #pragma unroll
        for (int j = 0; j < 2; j++) {
            float v = lsum[mt][j];
            v += __shfl_xor_sync(0xFFFFFFFF, v, 1);
            v += __shfl_xor_sync(0xFFFFFFFF, v, 2);
            lsum[mt][j] = v;
        }
    __syncthreads();
    if (tg == 0) {
        #pragma unroll
        for (int mt = 0; mt < 2; mt++) {
            lsh[wsi * QROWS + wq + mt * 16 + g]     = lsum[mt][0];
            lsh[wsi * QROWS + wq + mt * 16 + g + 8] = lsum[mt][1];
        }
    }
    __syncthreads();

    float inv[2][2];
    #pragma unroll
    for (int mt = 0; mt < 2; mt++) {
        int q_lo = wq + mt * 16 + g;
        inv[mt][0] = 1.f / (lsh[q_lo]     + lsh[QROWS + q_lo]);
        inv[mt][1] = 1.f / (lsh[q_lo + 8] + lsh[QROWS + q_lo + 8]);
    }

    __half* ob = g_attn16 + ((size_t)b * T + t0) * D + h * DKH;
    #pragma unroll
    for (int mt = 0; mt < 2; mt++) {
        int q_lo = wq + mt * 16 + g;
        int q_hi = q_lo + 8;
        #pragma unroll
        for (int nt = 0; nt < 6; nt++) {
            int dk = wsi * 48 + nt * 8 + 2 * tg;
            *(uint32_t*)(ob + (size_t)q_lo * D + dk) =
                h2bits(o[mt][nt][0] * inv[mt][0], o[mt][nt][1] * inv[mt][0]);
            *(uint32_t*)(ob + (size_t)q_hi * D + dk) =
                h2bits(o[mt][nt][2] * inv[mt][1], o[mt][nt][3] * inv[mt][1]);
        }
    }
}

// ---------------------------------------------------------------------------
extern "C" void kernel_launch(void* const* d_in, const int* in_sizes, int n_in,
                              void* d_out, int out_size) {
    const float* z  = (const float*)d_in[0];
    const float* mb = (const float*)d_in[1];
    const float* Wq = (const float*)d_in[2];
    const float* bq = (const float*)d_in[3];
    const float* Wk = (const float*)d_in[4];
    const float* bk = (const float*)d_in[5];
    const float* Wv = (const float*)d_in[6];
    const float* bv = (const float*)d_in[7];
    const float* Wo = (const float*)d_in[8];
    const float* bo = (const float*)d_in[9];
    float* out = (float*)d_out;

    const float alpha_q = 1.4426950408889634f / sqrtf(96.0f);

    // 0. Weight prep (fp16 conversion, alpha folded into Wq/bq)
    wprep_kernel<<<2, 256>>>(Wq, bq, Wo, alpha_q);

    // 1. K/V projection (batch-independent) -> fp16
    kv_proj_kernel<<<dim3(4, 24, 2), 256>>>(mb, Wk, bk, Wv, bv);

    uint32_t *dWq16, *dWo16; float* dbq;
    cudaGetSymbolAddress((void**)&dWq16, g_Wq16);
    cudaGetSymbolAddress((void**)&dWo16, g_Wo16);
    cudaGetSymbolAddress((void**)&dbq,  g_bq);

    // 2. Q projection -> g_q16 [b][t][d] fp16
    cudaFuncSetAttribute(proj16_kernel,
                         cudaFuncAttributeMaxDynamicSharedMemorySize, SMEM_PROJ_BYTES);
    proj16_kernel<<<dim3(32, 1, 16), 512, SMEM_PROJ_BYTES>>>(
        dWq16, dbq, z, 0, nullptr, 1);

    // 3. fp16 mma.sync attention (cp.async pipelined) -> g_attn16
    cudaFuncSetAttribute(attn_mma_kernel,
                         cudaFuncAttributeMaxDynamicSharedMemorySize, SMEM_ATTN_BYTES);
    attn_mma_kernel<<<dim3(T / QROWS, NH, B), 512, SMEM_ATTN_BYTES>>>();

    // 4. Output projection -> d_out fp32 [b][d][t]
    proj16_kernel<<<dim3(32, 1, 16), 512, SMEM_PROJ_BYTES>>>(
        dWo16, bo, nullptr, 1, out, 0);
}